// round 8
// baseline (speedup 1.0000x reference)
#include <cuda_runtime.h>
#include <cuda_bf16.h>
#include <math.h>
#include <stdint.h>

#define S_LEN   2048
#define DMODEL  2048
#define NHEADS  16
#define DK      128
#define NBATCH  4

// ---------------- static device scratch ------------------------------------
__device__ __nv_bfloat16 g_qhi[(size_t)NBATCH * S_LEN * DMODEL];
__device__ __nv_bfloat16 g_qlo[(size_t)NBATCH * S_LEN * DMODEL];
__device__ __nv_bfloat16 g_khi[(size_t)NBATCH * S_LEN * DMODEL];
__device__ __nv_bfloat16 g_klo[(size_t)NBATCH * S_LEN * DMODEL];
__device__ __nv_bfloat16 g_vhi[(size_t)NBATCH * S_LEN * DMODEL];
__device__ __nv_bfloat16 g_vlo[(size_t)NBATCH * S_LEN * DMODEL];
__device__ __nv_bfloat16 g_athi[(size_t)NBATCH * S_LEN * DMODEL];
__device__ __nv_bfloat16 g_atlo[(size_t)NBATCH * S_LEN * DMODEL];

// ======================= PTX helpers =======================================
__device__ __forceinline__ uint32_t smem_u32(const void* p) {
    uint32_t a;
    asm("{ .reg .u64 t; cvta.to.shared.u64 t, %1; cvt.u32.u64 %0, t; }" : "=r"(a) : "l"(p));
    return a;
}
#define CP_ASYNC16(dst, src) asm volatile("cp.async.cg.shared.global [%0], [%1], 16;" :: "r"(dst), "l"(src))
#define CP_COMMIT()          asm volatile("cp.async.commit_group;" ::: "memory")
#define CP_WAIT0()           asm volatile("cp.async.wait_group 0;" ::: "memory")
#define CP_WAIT1()           asm volatile("cp.async.wait_group 1;" ::: "memory")

#define LDSM_X4(r0, r1, r2, r3, addr) \
    asm volatile("ldmatrix.sync.aligned.m8n8.x4.shared.b16 {%0,%1,%2,%3}, [%4];" \
        : "=r"(r0), "=r"(r1), "=r"(r2), "=r"(r3) : "r"(addr))
#define LDSM_X4_T(r0, r1, r2, r3, addr) \
    asm volatile("ldmatrix.sync.aligned.m8n8.x4.trans.shared.b16 {%0,%1,%2,%3}, [%4];" \
        : "=r"(r0), "=r"(r1), "=r"(r2), "=r"(r3) : "r"(addr))

#define MMA_BF16(c, a, b0, b1) \
    asm volatile("mma.sync.aligned.m16n8k16.row.col.f32.bf16.bf16.f32 " \
        "{%0,%1,%2,%3},{%4,%5,%6,%7},{%8,%9},{%0,%1,%2,%3};" \
        : "+f"((c)[0]), "+f"((c)[1]), "+f"((c)[2]), "+f"((c)[3]) \
        : "r"((a)[0]), "r"((a)[1]), "r"((a)[2]), "r"((a)[3]), "r"(b0), "r"(b1))

__device__ __forceinline__ void split2(float x, __nv_bfloat16& h, __nv_bfloat16& l) {
    h = __float2bfloat16_rn(x);
    l = __float2bfloat16_rn(x - __bfloat162float(h));
}
__device__ __forceinline__ uint32_t packb(__nv_bfloat16 a, __nv_bfloat16 b) {
    __nv_bfloat162 t(a, b);
    return *(uint32_t*)&t;
}

// ===========================================================================
// smem geometry shared by the projection GEMMs
// ===========================================================================
#define LDSB 80
#define ARR_BYTES (128 * LDSB)      // 10240
#define STG_BYTES (4 * ARR_BYTES)   // 40960  (Ahi, Alo, Bhi, Blo)
#define NT_SMEM (2 * STG_BYTES)     // 81920

// ===========================================================================
// QKV projection: one launch, grid.z in {0,1,2} selects (x, W, out).
// A and B read as raw fp32 and split to bf16 hi/lo in-kernel.
// C[m,n] = sum_k A[m,k] * B[n,k], written as bf16 hi/lo.
// ===========================================================================
__global__ __launch_bounds__(256) void gemm_qkv(
    const float* __restrict__ x0, const float* __restrict__ x1, const float* __restrict__ x2,
    const float* __restrict__ w0, const float* __restrict__ w1, const float* __restrict__ w2,
    __nv_bfloat16* __restrict__ o0h, __nv_bfloat16* __restrict__ o0l,
    __nv_bfloat16* __restrict__ o1h, __nv_bfloat16* __restrict__ o1l,
    __nv_bfloat16* __restrict__ o2h, __nv_bfloat16* __restrict__ o2l)
{
    extern __shared__ char smem[];
    const uint32_t sb = smem_u32(smem);
    const int tid  = threadIdx.x;
    const int lane = tid & 31, wid = tid >> 5;
    const int wm   = wid & 3, wn = wid >> 2;
    const int row0 = blockIdx.y * 128;
    const int col0 = blockIdx.x * 128;
    const int z    = blockIdx.z;

    const float* Af = (z == 0) ? x0 : ((z == 1) ? x1 : x2);
    const float* Bf = (z == 0) ? w0 : ((z == 1) ? w1 : w2);
    __nv_bfloat16* Ch = (z == 0) ? o0h : ((z == 1) ? o1h : o2h);
    __nv_bfloat16* Cl = (z == 0) ? o0l : ((z == 1) ? o1l : o2l);

    const int nchunk = DMODEL >> 5;  // 64

    float4 pa[4], pb[4];
    auto ldg_stage = [&](int kt) {
        const int k0 = kt << 5;
#pragma unroll
        for (int i = 0; i < 4; i++) {
            const int c = tid + i * 256;        // 0..1023
            const int r = c >> 3, qd = c & 7;   // row 0..127, col-group 0..7
            pa[i] = *(const float4*)(Af + (size_t)(row0 + r) * DMODEL + k0 + qd * 4);
            pb[i] = *(const float4*)(Bf + (size_t)(col0 + r) * DMODEL + k0 + qd * 4);
        }
    };
    auto sts_stage = [&](int s) {
        char* sbase = smem + s * STG_BYTES;
#pragma unroll
        for (int i = 0; i < 4; i++) {
            const int c = tid + i * 256;
            const int r = c >> 3, qd = c & 7;
            const int off = r * LDSB + qd * 8;
            __nv_bfloat16 h0, h1, h2, h3, l0, l1, l2, l3;
            split2(pa[i].x, h0, l0); split2(pa[i].y, h1, l1);
            split2(pa[i].z, h2, l2); split2(pa[i].w, h3, l3);
            *(uint2*)(sbase + 0 * ARR_BYTES + off) = make_uint2(packb(h0, h1), packb(h2, h3));
            *(uint2*)(sbase + 1 * ARR_BYTES + off) = make_uint2(packb(l0, l1), packb(l2, l3));
            split2(pb[i].x, h0, l0); split2(pb[i].y, h1, l1);
            split2(pb[i].z, h2, l2); split2(pb[i].w, h3, l3);
            *(uint2*)(sbase + 2 * ARR_BYTES + off) = make_uint2(packb(h0, h1), packb(h2, h3));
            *(uint2*)(sbase + 3 * ARR_BYTES + off) = make_uint2(packb(l0, l1), packb(l2, l3));
        }
    };

    float acc[2][8][4];
#pragma unroll
    for (int mt = 0; mt < 2; mt++)
#pragma unroll
        for (int nt = 0; nt < 8; nt++)
#pragma unroll
            for (int r = 0; r < 4; r++) acc[mt][nt][r] = 0.0f;

    const int arow  = wm * 32 + (lane & 15);
    const int acolb = ((lane >> 4) << 3) * 2;
    const int brow  = wn * 64 + (lane & 7) + ((lane >> 4) & 1) * 8;
    const int bcolb = (((lane >> 3) & 1) << 3) * 2;

    auto compute_stage = [&](int s) {
        const uint32_t sbase = sb + s * STG_BYTES;
        const uint32_t sAhi = sbase;
        const uint32_t sAlo = sbase + ARR_BYTES;
        const uint32_t sBhi = sbase + 2 * ARR_BYTES;
        const uint32_t sBlo = sbase + 3 * ARR_BYTES;
#pragma unroll
        for (int h = 0; h < 2; h++) {
            const int kb = h * 32;
            uint32_t ah[4], al[4], ah1[4], al1[4];
            {
                uint32_t a0 = sAhi + arow * LDSB + acolb + kb;
                LDSM_X4(ah[0], ah[1], ah[2], ah[3], a0);
                LDSM_X4(ah1[0], ah1[1], ah1[2], ah1[3], a0 + 16 * LDSB);
                uint32_t l0 = sAlo + arow * LDSB + acolb + kb;
                LDSM_X4(al[0], al[1], al[2], al[3], l0);
                LDSM_X4(al1[0], al1[1], al1[2], al1[3], l0 + 16 * LDSB);
            }
#pragma unroll
            for (int np = 0; np < 4; np++) {
                uint32_t bh[4], bl[4];
                const uint32_t bo = (brow + np * 16) * LDSB + bcolb + kb;
                LDSM_X4(bh[0], bh[1], bh[2], bh[3], sBhi + bo);
                LDSM_X4(bl[0], bl[1], bl[2], bl[3], sBlo + bo);
#pragma unroll
                for (int u = 0; u < 2; u++) {
                    float* c0 = acc[0][np * 2 + u];
                    MMA_BF16(c0, ah, bh[2 * u], bh[2 * u + 1]);
                    MMA_BF16(c0, ah, bl[2 * u], bl[2 * u + 1]);
                    MMA_BF16(c0, al, bh[2 * u], bh[2 * u + 1]);
                    float* c1 = acc[1][np * 2 + u];
                    MMA_BF16(c1, ah1, bh[2 * u], bh[2 * u + 1]);
                    MMA_BF16(c1, ah1, bl[2 * u], bl[2 * u + 1]);
                    MMA_BF16(c1, al1, bh[2 * u], bh[2 * u + 1]);
                }
            }
        }
    };

    ldg_stage(0);
    sts_stage(0);
    for (int t = 0; t < nchunk; t++) {
        if (t + 1 < nchunk) ldg_stage(t + 1);
        __syncthreads();
        compute_stage(t & 1);
        __syncthreads();
        if (t + 1 < nchunk) sts_stage((t + 1) & 1);
    }

#pragma unroll
    for (int mt = 0; mt < 2; mt++) {
#pragma unroll
        for (int nt = 0; nt < 8; nt++) {
            const int r  = row0 + wm * 32 + mt * 16 + (lane >> 2);
            const int cc = col0 + wn * 64 + nt * 8 + (lane & 3) * 2;
            __nv_bfloat16 h0, h1, l0, l1;
            split2(acc[mt][nt][0], h0, l0);
            split2(acc[mt][nt][1], h1, l1);
            *(__nv_bfloat162*)(Ch + (size_t)r * DMODEL + cc) = __nv_bfloat162(h0, h1);
            *(__nv_bfloat162*)(Cl + (size_t)r * DMODEL + cc) = __nv_bfloat162(l0, l1);
            split2(acc[mt][nt][2], h0, l0);
            split2(acc[mt][nt][3], h1, l1);
            *(__nv_bfloat162*)(Ch + (size_t)(r + 8) * DMODEL + cc) = __nv_bfloat162(h0, h1);
            *(__nv_bfloat162*)(Cl + (size_t)(r + 8) * DMODEL + cc) = __nv_bfloat162(l0, l1);
        }
    }
}

// ===========================================================================
// W_o projection: A = attn (pre-split bf16 hi/lo, cp.async), B = w_o fp32
// split in-kernel. C fp32 -> d_out.
// ===========================================================================
__global__ __launch_bounds__(256) void gemm_wo(
    const __nv_bfloat16* __restrict__ Ahi, const __nv_bfloat16* __restrict__ Alo,
    const float* __restrict__ Bf, float* __restrict__ Cf)
{
    extern __shared__ char smem[];
    const uint32_t sb = smem_u32(smem);
    const int tid  = threadIdx.x;
    const int lane = tid & 31, wid = tid >> 5;
    const int wm   = wid & 3, wn = wid >> 2;
    const int row0 = blockIdx.y * 128;
    const int col0 = blockIdx.x * 128;

    const int nchunk = DMODEL >> 5;

    float4 pb[4];
    auto ldgB = [&](int kt) {
        const int k0 = kt << 5;
#pragma unroll
        for (int i = 0; i < 4; i++) {
            const int c = tid + i * 256;
            const int r = c >> 3, qd = c & 7;
            pb[i] = *(const float4*)(Bf + (size_t)(col0 + r) * DMODEL + k0 + qd * 4);
        }
    };
    auto stsB = [&](int s) {
        char* sbase = smem + s * STG_BYTES;
#pragma unroll
        for (int i = 0; i < 4; i++) {
            const int c = tid + i * 256;
            const int r = c >> 3, qd = c & 7;
            const int off = r * LDSB + qd * 8;
            __nv_bfloat16 h0, h1, h2, h3, l0, l1, l2, l3;
            split2(pb[i].x, h0, l0); split2(pb[i].y, h1, l1);
            split2(pb[i].z, h2, l2); split2(pb[i].w, h3, l3);
            *(uint2*)(sbase + 2 * ARR_BYTES + off) = make_uint2(packb(h0, h1), packb(h2, h3));
            *(uint2*)(sbase + 3 * ARR_BYTES + off) = make_uint2(packb(l0, l1), packb(l2, l3));
        }
    };
    auto cpA = [&](int kt, int s) {
        const int k0 = kt << 5;
        const uint32_t sbase = sb + s * STG_BYTES;
#pragma unroll
        for (int a = 0; a < 2; a++) {
            const __nv_bfloat16* g = (a == 0) ? Ahi : Alo;
#pragma unroll
            for (int i = 0; i < 2; i++) {
                const int c = tid + i * 256;
                const int r = c >> 2, q = c & 3;
                CP_ASYNC16(sbase + a * ARR_BYTES + r * LDSB + q * 16,
                           g + (size_t)(row0 + r) * DMODEL + k0 + q * 8);
            }
        }
        CP_COMMIT();
    };

    float acc[2][8][4];
#pragma unroll
    for (int mt = 0; mt < 2; mt++)
#pragma unroll
        for (int nt = 0; nt < 8; nt++)
#pragma unroll
            for (int r = 0; r < 4; r++) acc[mt][nt][r] = 0.0f;

    const int arow  = wm * 32 + (lane & 15);
    const int acolb = ((lane >> 4) << 3) * 2;
    const int brow  = wn * 64 + (lane & 7) + ((lane >> 4) & 1) * 8;
    const int bcolb = (((lane >> 3) & 1) << 3) * 2;

    auto compute_stage = [&](int s) {
        const uint32_t sbase = sb + s * STG_BYTES;
        const uint32_t sAhi = sbase;
        const uint32_t sAlo = sbase + ARR_BYTES;
        const uint32_t sBhi = sbase + 2 * ARR_BYTES;
        const uint32_t sBlo = sbase + 3 * ARR_BYTES;
#pragma unroll
        for (int h = 0; h < 2; h++) {
            const int kb = h * 32;
            uint32_t ah[4], al[4], ah1[4], al1[4];
            {
                uint32_t a0 = sAhi + arow * LDSB + acolb + kb;
                LDSM_X4(ah[0], ah[1], ah[2], ah[3], a0);
                LDSM_X4(ah1[0], ah1[1], ah1[2], ah1[3], a0 + 16 * LDSB);
                uint32_t l0 = sAlo + arow * LDSB + acolb + kb;
                LDSM_X4(al[0], al[1], al[2], al[3], l0);
                LDSM_X4(al1[0], al1[1], al1[2], al1[3], l0 + 16 * LDSB);
            }
#pragma unroll
            for (int np = 0; np < 4; np++) {
                uint32_t bh[4], bl[4];
                const uint32_t bo = (brow + np * 16) * LDSB + bcolb + kb;
                LDSM_X4(bh[0], bh[1], bh[2], bh[3], sBhi + bo);
                LDSM_X4(bl[0], bl[1], bl[2], bl[3], sBlo + bo);
#pragma unroll
                for (int u = 0; u < 2; u++) {
                    float* c0 = acc[0][np * 2 + u];
                    MMA_BF16(c0, ah, bh[2 * u], bh[2 * u + 1]);
                    MMA_BF16(c0, ah, bl[2 * u], bl[2 * u + 1]);
                    MMA_BF16(c0, al, bh[2 * u], bh[2 * u + 1]);
                    float* c1 = acc[1][np * 2 + u];
                    MMA_BF16(c1, ah1, bh[2 * u], bh[2 * u + 1]);
                    MMA_BF16(c1, ah1, bl[2 * u], bl[2 * u + 1]);
                    MMA_BF16(c1, al1, bh[2 * u], bh[2 * u + 1]);
                }
            }
        }
    };

    ldgB(0);
    cpA(0, 0);
    stsB(0);
    for (int t = 0; t < nchunk; t++) {
        if (t + 1 < nchunk) { ldgB(t + 1); cpA(t + 1, (t + 1) & 1); }
        if (t + 1 < nchunk) { CP_WAIT1(); } else { CP_WAIT0(); }
        __syncthreads();
        compute_stage(t & 1);
        __syncthreads();
        if (t + 1 < nchunk) stsB((t + 1) & 1);
    }

#pragma unroll
    for (int mt = 0; mt < 2; mt++) {
#pragma unroll
        for (int nt = 0; nt < 8; nt++) {
            const int r  = row0 + wm * 32 + mt * 16 + (lane >> 2);
            const int cc = col0 + wn * 64 + nt * 8 + (lane & 3) * 2;
            float* p = Cf + (size_t)r * DMODEL + cc;
            *(float2*)p = make_float2(acc[mt][nt][0], acc[mt][nt][1]);
            *(float2*)(p + 8 * DMODEL) = make_float2(acc[mt][nt][2], acc[mt][nt][3]);
        }
    }
}

// ===========================================================================
// Fused flash attention (unchanged from Round 7)
// ===========================================================================
#define FA_LDSB    272
#define FA_QTILE   (128 * FA_LDSB)
#define FA_KVTILE  (64 * FA_LDSB)
#define FA_STG     (4 * FA_KVTILE)
#define FA_SMEM    (2 * FA_QTILE + 2 * FA_STG)  // 208896

__global__ __launch_bounds__(256, 1) void fused_attn(
    const __nv_bfloat16* __restrict__ Qhi, const __nv_bfloat16* __restrict__ Qlo,
    const __nv_bfloat16* __restrict__ Khi, const __nv_bfloat16* __restrict__ Klo,
    const __nv_bfloat16* __restrict__ Vhi, const __nv_bfloat16* __restrict__ Vlo,
    __nv_bfloat16* __restrict__ Ohi, __nv_bfloat16* __restrict__ Olo)
{
    extern __shared__ char smem[];
    const uint32_t sb = smem_u32(smem);
    const int tid  = threadIdx.x;
    const int lane = tid & 31, wid = tid >> 5;
    const int qrow0 = blockIdx.x * 128;
    const int z  = blockIdx.y;
    const int bb = z >> 4, hh = z & 15;
    const size_t base = (size_t)bb * S_LEN * DMODEL + (size_t)hh * DK;

    const __nv_bfloat16* qsrc[2] = {Qhi + base, Qlo + base};
    const __nv_bfloat16* kvsrc[4] = {Khi + base, Klo + base, Vhi + base, Vlo + base};

    const uint32_t sQ = sb;
    const uint32_t sKV = sb + 2 * FA_QTILE;

#pragma unroll
    for (int i = 0; i < 16; i++) {
        const int c = tid + i * 256;
        const int t = c >> 11, rem = c & 2047;
        const int r = rem >> 4, q = rem & 15;
        CP_ASYNC16(sQ + t * FA_QTILE + r * FA_LDSB + q * 16,
                   qsrc[t] + (size_t)(qrow0 + r) * DMODEL + q * 8);
    }
    auto issue_stage = [&](int j, int s) {
        const int s0 = j << 6;
        const uint32_t sbase = sKV + s * FA_STG;
#pragma unroll
        for (int i = 0; i < 16; i++) {
            const int c = tid + i * 256;
            const int t = c >> 10, rem = c & 1023;
            const int r = rem >> 4, q = rem & 15;
            CP_ASYNC16(sbase + t * FA_KVTILE + r * FA_LDSB + q * 16,
                       kvsrc[t] + (size_t)(s0 + r) * DMODEL + q * 8);
        }
        CP_COMMIT();
    };
    issue_stage(0, 0);
    issue_stage(1, 1);

    float accO[16][4];
#pragma unroll
    for (int nt = 0; nt < 16; nt++)
#pragma unroll
        for (int r = 0; r < 4; r++) accO[nt][r] = 0.0f;
    float mrow[2] = {-1e30f, -1e30f};
    float lrow[2] = {0.0f, 0.0f};
    const float csc = 0.08838834764831845f;

    const int arow  = wid * 16 + (lane & 15);
    const int acolb = (lane >> 4) * 16;
    const int brow  = (lane & 7) + ((lane >> 4) & 1) * 8;
    const int bcolb = ((lane >> 3) & 1) * 16;
    const int btr   = (lane & 7) + ((lane >> 3) & 1) * 8;
    const int btc   = ((lane >> 4) & 1) * 8;

    const int NITER = S_LEN / 64;
    for (int j = 0; j < NITER; j++) {
        if (j + 2 < NITER) { CP_WAIT1(); } else { CP_WAIT0(); }
        __syncthreads();
        const uint32_t st = sKV + (j & 1) * FA_STG;
        const uint32_t sKh = st;
        const uint32_t sKl = st + FA_KVTILE;
        const uint32_t sVh = st + 2 * FA_KVTILE;
        const uint32_t sVl = st + 3 * FA_KVTILE;

        float sacc[8][4];
#pragma unroll
        for (int nt = 0; nt < 8; nt++)
#pragma unroll
            for (int r = 0; r < 4; r++) sacc[nt][r] = 0.0f;

#pragma unroll
        for (int kst = 0; kst < 8; kst++) {
            const int kb = kst * 32;
            uint32_t qh[4], ql[4];
            LDSM_X4(qh[0], qh[1], qh[2], qh[3], sQ + arow * FA_LDSB + acolb + kb);
            LDSM_X4(ql[0], ql[1], ql[2], ql[3], sQ + FA_QTILE + arow * FA_LDSB + acolb + kb);
#pragma unroll
            for (int np = 0; np < 4; np++) {
                const uint32_t bo = (uint32_t)(brow + np * 16) * FA_LDSB + bcolb + kb;
                uint32_t kh[4], kl[4];
                LDSM_X4(kh[0], kh[1], kh[2], kh[3], sKh + bo);
                LDSM_X4(kl[0], kl[1], kl[2], kl[3], sKl + bo);
#pragma unroll
                for (int u = 0; u < 2; u++) {
                    float* c = sacc[np * 2 + u];
                    MMA_BF16(c, qh, kh[2 * u], kh[2 * u + 1]);
                    MMA_BF16(c, qh, kl[2 * u], kl[2 * u + 1]);
                    MMA_BF16(c, ql, kh[2 * u], kh[2 * u + 1]);
                }
            }
        }

        float mnew[2] = {mrow[0], mrow[1]};
#pragma unroll
        for (int nt = 0; nt < 8; nt++) {
            mnew[0] = fmaxf(mnew[0], fmaxf(sacc[nt][0], sacc[nt][1]));
            mnew[1] = fmaxf(mnew[1], fmaxf(sacc[nt][2], sacc[nt][3]));
        }
#pragma unroll
        for (int o = 1; o <= 2; o <<= 1) {
            mnew[0] = fmaxf(mnew[0], __shfl_xor_sync(0xffffffffu, mnew[0], o));
            mnew[1] = fmaxf(mnew[1], __shfl_xor_sync(0xffffffffu, mnew[1], o));
        }
        const float sc0 = __expf((mrow[0] - mnew[0]) * csc);
        const float sc1 = __expf((mrow[1] - mnew[1]) * csc);
        mrow[0] = mnew[0]; mrow[1] = mnew[1];
        lrow[0] *= sc0; lrow[1] *= sc1;
#pragma unroll
        for (int nt = 0; nt < 16; nt++) {
            accO[nt][0] *= sc0; accO[nt][1] *= sc0;
            accO[nt][2] *= sc1; accO[nt][3] *= sc1;
        }

        uint32_t ph[4][4], pl[4][4];
        float ls0 = 0.0f, ls1 = 0.0f;
#pragma unroll
        for (int t2 = 0; t2 < 4; t2++) {
#pragma unroll
            for (int half = 0; half < 2; half++) {
                float* s = sacc[2 * t2 + half];
                float p0 = __expf((s[0] - mnew[0]) * csc);
                float p1 = __expf((s[1] - mnew[0]) * csc);
                float p2 = __expf((s[2] - mnew[1]) * csc);
                float p3 = __expf((s[3] - mnew[1]) * csc);
                ls0 += p0 + p1; ls1 += p2 + p3;
                __nv_bfloat16 h0, h1, h2, h3, l0, l1, l2, l3;
                split2(p0, h0, l0); split2(p1, h1, l1);
                split2(p2, h2, l2); split2(p3, h3, l3);
                ph[t2][2 * half + 0] = packb(h0, h1);
                ph[t2][2 * half + 1] = packb(h2, h3);
                pl[t2][2 * half + 0] = packb(l0, l1);
                pl[t2][2 * half + 1] = packb(l2, l3);
            }
        }
        lrow[0] += ls0; lrow[1] += ls1;

#pragma unroll
        for (int t2 = 0; t2 < 4; t2++) {
#pragma unroll
            for (int np = 0; np < 8; np++) {
                const uint32_t bo = (uint32_t)(t2 * 16 + btr) * FA_LDSB + (np * 16 + btc) * 2;
                uint32_t vh[4], vl[4];
                LDSM_X4_T(vh[0], vh[1], vh[2], vh[3], sVh + bo);
                LDSM_X4_T(vl[0], vl[1], vl[2], vl[3], sVl + bo);
#pragma unroll
                for (int u = 0; u < 2; u++) {
                    float* c = accO[np * 2 + u];
                    MMA_BF16(c, ph[t2], vh[2 * u], vh[2 * u + 1]);
                    MMA_BF16(c, ph[t2], vl[2 * u], vl[2 * u + 1]);
                    MMA_BF16(c, pl[t2], vh[2 * u], vh[2 * u + 1]);
                }
            }
        }

        __syncthreads();
        if (j + 2 < NITER) issue_stage(j + 2, j & 1);
    }

#pragma unroll
    for (int o = 1; o <= 2; o <<= 1) {
        lrow[0] += __shfl_xor_sync(0xffffffffu, lrow[0], o);
        lrow[1] += __shfl_xor_sync(0xffffffffu, lrow[1], o);
    }
    const float inv0 = 1.0f / lrow[0];
    const float inv1 = 1.0f / lrow[1];
    const int r0 = qrow0 + wid * 16 + (lane >> 2);
#pragma unroll
    for (int nt = 0; nt < 16; nt++) {
        const int cc = nt * 8 + (lane & 3) * 2;
        __nv_bfloat16 h0, h1, l0, l1;
        split2(accO[nt][0] * inv0, h0, l0);
        split2(accO[nt][1] * inv0, h1, l1);
        *(__nv_bfloat162*)(Ohi + base + (size_t)r0 * DMODEL + cc) = __nv_bfloat162(h0, h1);
        *(__nv_bfloat162*)(Olo + base + (size_t)r0 * DMODEL + cc) = __nv_bfloat162(l0, l1);
        split2(accO[nt][2] * inv1, h0, l0);
        split2(accO[nt][3] * inv1, h1, l1);
        *(__nv_bfloat162*)(Ohi + base + (size_t)(r0 + 8) * DMODEL + cc) = __nv_bfloat162(h0, h1);
        *(__nv_bfloat162*)(Olo + base + (size_t)(r0 + 8) * DMODEL + cc) = __nv_bfloat162(l0, l1);
    }
}

// ---------------------------------------------------------------------------
extern "C" void kernel_launch(void* const* d_in, const int* in_sizes, int n_in,
                              void* d_out, int out_size)
{
    const float* q   = (const float*)d_in[0];
    const float* k   = (const float*)d_in[1];
    const float* v   = (const float*)d_in[2];
    const float* w_q = (const float*)d_in[3];
    const float* w_k = (const float*)d_in[4];
    const float* w_v = (const float*)d_in[5];
    const float* w_o = (const float*)d_in[6];
    float* out = (float*)d_out;

    __nv_bfloat16 *qhi, *qlo, *khi, *klo, *vhi, *vlo, *athi, *atlo;
    cudaGetSymbolAddress((void**)&qhi, g_qhi);  cudaGetSymbolAddress((void**)&qlo, g_qlo);
    cudaGetSymbolAddress((void**)&khi, g_khi);  cudaGetSymbolAddress((void**)&klo, g_klo);
    cudaGetSymbolAddress((void**)&vhi, g_vhi);  cudaGetSymbolAddress((void**)&vlo, g_vlo);
    cudaGetSymbolAddress((void**)&athi, g_athi); cudaGetSymbolAddress((void**)&atlo, g_atlo);

    cudaFuncSetAttribute(gemm_qkv, cudaFuncAttributeMaxDynamicSharedMemorySize, NT_SMEM);
    cudaFuncSetAttribute(gemm_wo, cudaFuncAttributeMaxDynamicSharedMemorySize, NT_SMEM);
    cudaFuncSetAttribute(fused_attn, cudaFuncAttributeMaxDynamicSharedMemorySize, FA_SMEM);

    const int M_rows = NBATCH * S_LEN;
    dim3 blk(256);

    // 1) Q/K/V projections in one launch, split fused into loaders + epilogue
    {
        dim3 grid(DMODEL / 128, M_rows / 128, 3);
        gemm_qkv<<<grid, blk, NT_SMEM>>>(q, k, v, w_q, w_k, w_v,
                                         qhi, qlo, khi, klo, vhi, vlo);
    }

    // 2) Fused attention (QK^T -> online softmax -> PV), attn as hi/lo
    {
        dim3 grid(S_LEN / 128, NBATCH * NHEADS);
        fused_attn<<<grid, blk, FA_SMEM>>>(qhi, qlo, khi, klo, vhi, vlo, athi, atlo);
    }

    // 3) Output projection -> fp32 d_out (w_o split fused into loader)
    {
        dim3 grid(DMODEL / 128, M_rows / 128);
        gemm_wo<<<grid, blk, NT_SMEM>>>(athi, atlo, w_o, out);
    }
}

// round 9
// speedup vs baseline: 1.1019x; 1.1019x over previous
#include <cuda_runtime.h>
#include <cuda_bf16.h>
#include <math.h>
#include <stdint.h>

#define S_LEN   2048
#define DMODEL  2048
#define NHEADS  16
#define DK      128
#define NBATCH  4

// ---------------- static device scratch ------------------------------------
__device__ __nv_bfloat16 g_qhi[(size_t)NBATCH * S_LEN * DMODEL];
__device__ __nv_bfloat16 g_qlo[(size_t)NBATCH * S_LEN * DMODEL];
__device__ __nv_bfloat16 g_khi[(size_t)NBATCH * S_LEN * DMODEL];
__device__ __nv_bfloat16 g_klo[(size_t)NBATCH * S_LEN * DMODEL];
__device__ __nv_bfloat16 g_vhi[(size_t)NBATCH * S_LEN * DMODEL];
__device__ __nv_bfloat16 g_vlo[(size_t)NBATCH * S_LEN * DMODEL];
__device__ __nv_bfloat16 g_athi[(size_t)NBATCH * S_LEN * DMODEL];
__device__ __nv_bfloat16 g_atlo[(size_t)NBATCH * S_LEN * DMODEL];
// split activations (q,k,v inputs)
__device__ __nv_bfloat16 g_xqh[(size_t)NBATCH * S_LEN * DMODEL];
__device__ __nv_bfloat16 g_xql[(size_t)NBATCH * S_LEN * DMODEL];
__device__ __nv_bfloat16 g_xkh[(size_t)NBATCH * S_LEN * DMODEL];
__device__ __nv_bfloat16 g_xkl[(size_t)NBATCH * S_LEN * DMODEL];
__device__ __nv_bfloat16 g_xvh[(size_t)NBATCH * S_LEN * DMODEL];
__device__ __nv_bfloat16 g_xvl[(size_t)NBATCH * S_LEN * DMODEL];
// split weights (all four)
__device__ __nv_bfloat16 g_wqh[(size_t)DMODEL * DMODEL];
__device__ __nv_bfloat16 g_wql[(size_t)DMODEL * DMODEL];
__device__ __nv_bfloat16 g_wkh[(size_t)DMODEL * DMODEL];
__device__ __nv_bfloat16 g_wkl[(size_t)DMODEL * DMODEL];
__device__ __nv_bfloat16 g_wvh[(size_t)DMODEL * DMODEL];
__device__ __nv_bfloat16 g_wvl[(size_t)DMODEL * DMODEL];
__device__ __nv_bfloat16 g_woh[(size_t)DMODEL * DMODEL];
__device__ __nv_bfloat16 g_wol[(size_t)DMODEL * DMODEL];

// ======================= PTX helpers =======================================
__device__ __forceinline__ uint32_t smem_u32(const void* p) {
    uint32_t a;
    asm("{ .reg .u64 t; cvta.to.shared.u64 t, %1; cvt.u32.u64 %0, t; }" : "=r"(a) : "l"(p));
    return a;
}
#define CP_ASYNC16(dst, src) asm volatile("cp.async.cg.shared.global [%0], [%1], 16;" :: "r"(dst), "l"(src))
#define CP_COMMIT()          asm volatile("cp.async.commit_group;" ::: "memory")
#define CP_WAIT0()           asm volatile("cp.async.wait_group 0;" ::: "memory")
#define CP_WAIT1()           asm volatile("cp.async.wait_group 1;" ::: "memory")

#define LDSM_X4(r0, r1, r2, r3, addr) \
    asm volatile("ldmatrix.sync.aligned.m8n8.x4.shared.b16 {%0,%1,%2,%3}, [%4];" \
        : "=r"(r0), "=r"(r1), "=r"(r2), "=r"(r3) : "r"(addr))
#define LDSM_X4_T(r0, r1, r2, r3, addr) \
    asm volatile("ldmatrix.sync.aligned.m8n8.x4.trans.shared.b16 {%0,%1,%2,%3}, [%4];" \
        : "=r"(r0), "=r"(r1), "=r"(r2), "=r"(r3) : "r"(addr))

#define MMA_BF16(c, a, b0, b1) \
    asm volatile("mma.sync.aligned.m16n8k16.row.col.f32.bf16.bf16.f32 " \
        "{%0,%1,%2,%3},{%4,%5,%6,%7},{%8,%9},{%0,%1,%2,%3};" \
        : "+f"((c)[0]), "+f"((c)[1]), "+f"((c)[2]), "+f"((c)[3]) \
        : "r"((a)[0]), "r"((a)[1]), "r"((a)[2]), "r"((a)[3]), "r"(b0), "r"(b1))

__device__ __forceinline__ void split2(float x, __nv_bfloat16& h, __nv_bfloat16& l) {
    h = __float2bfloat16_rn(x);
    l = __float2bfloat16_rn(x - __bfloat162float(h));
}
__device__ __forceinline__ uint32_t packb(__nv_bfloat16 a, __nv_bfloat16 b) {
    __nv_bfloat162 t(a, b);
    return *(uint32_t*)&t;
}

// ===========================================================================
// bf16x3 NT GEMM body (cp.async loaders, pre-split operands)
// C[m,n] = sum_k A[m,k]*B[n,k]; K = lda = ldb = ldc = DMODEL
// ===========================================================================
#define LDSB 80
#define ARR_BYTES (128 * LDSB)
#define STG_BYTES (4 * ARR_BYTES)
#define NT_SMEM (2 * STG_BYTES)     // 81920

template<int OUTMODE>
__device__ __forceinline__ void gemm_body(
    const __nv_bfloat16* __restrict__ Ahi, const __nv_bfloat16* __restrict__ Alo,
    const __nv_bfloat16* __restrict__ Bhi, const __nv_bfloat16* __restrict__ Blo,
    float* __restrict__ Cf, __nv_bfloat16* __restrict__ Chi, __nv_bfloat16* __restrict__ Clo)
{
    extern __shared__ char smem[];
    const uint32_t sb = smem_u32(smem);
    const int tid  = threadIdx.x;
    const int lane = tid & 31, wid = tid >> 5;
    const int wm   = wid & 3, wn = wid >> 2;
    const int row0 = blockIdx.y * 128;
    const int col0 = blockIdx.x * 128;

    const __nv_bfloat16* gsrc[4] = {Ahi, Alo, Bhi, Blo};
    const int nchunk = DMODEL >> 5;   // 64

    auto issue_stage = [&](int kt, int s) {
        const int k0 = kt << 5;
        const uint32_t sbase = sb + s * STG_BYTES;
#pragma unroll
        for (int a = 0; a < 4; a++) {
            const __nv_bfloat16* g = gsrc[a];
            const int rbase = (a < 2) ? row0 : col0;
#pragma unroll
            for (int i = 0; i < 2; i++) {
                const int c = tid + i * 256;
                const int r = c >> 2, q = c & 3;
                CP_ASYNC16(sbase + a * ARR_BYTES + r * LDSB + q * 16,
                           g + (size_t)(rbase + r) * DMODEL + k0 + q * 8);
            }
        }
        CP_COMMIT();
    };

    float acc[2][8][4];
#pragma unroll
    for (int mt = 0; mt < 2; mt++)
#pragma unroll
        for (int nt = 0; nt < 8; nt++)
#pragma unroll
            for (int r = 0; r < 4; r++) acc[mt][nt][r] = 0.0f;

    const int arow  = wm * 32 + (lane & 15);
    const int acolb = ((lane >> 4) << 3) * 2;
    const int brow  = wn * 64 + (lane & 7) + ((lane >> 4) & 1) * 8;
    const int bcolb = (((lane >> 3) & 1) << 3) * 2;

    auto compute_stage = [&](int s) {
        const uint32_t sbase = sb + s * STG_BYTES;
        const uint32_t sAhi = sbase;
        const uint32_t sAlo = sbase + ARR_BYTES;
        const uint32_t sBhi = sbase + 2 * ARR_BYTES;
        const uint32_t sBlo = sbase + 3 * ARR_BYTES;
#pragma unroll
        for (int h = 0; h < 2; h++) {
            const int kb = h * 32;
            uint32_t ah[2][4], al[2][4];
            {
                uint32_t a0 = sAhi + arow * LDSB + acolb + kb;
                LDSM_X4(ah[0][0], ah[0][1], ah[0][2], ah[0][3], a0);
                LDSM_X4(ah[1][0], ah[1][1], ah[1][2], ah[1][3], a0 + 16 * LDSB);
                uint32_t l0 = sAlo + arow * LDSB + acolb + kb;
                LDSM_X4(al[0][0], al[0][1], al[0][2], al[0][3], l0);
                LDSM_X4(al[1][0], al[1][1], al[1][2], al[1][3], l0 + 16 * LDSB);
            }
#pragma unroll
            for (int np = 0; np < 4; np++) {
                uint32_t bh[4], bl[4];
                const uint32_t bo = (brow + np * 16) * LDSB + bcolb + kb;
                LDSM_X4(bh[0], bh[1], bh[2], bh[3], sBhi + bo);
                LDSM_X4(bl[0], bl[1], bl[2], bl[3], sBlo + bo);
#pragma unroll
                for (int mt = 0; mt < 2; mt++) {
#pragma unroll
                    for (int u = 0; u < 2; u++) {
                        float* c = acc[mt][np * 2 + u];
                        MMA_BF16(c, ah[mt], bh[2 * u], bh[2 * u + 1]);
                        MMA_BF16(c, ah[mt], bl[2 * u], bl[2 * u + 1]);
                        MMA_BF16(c, al[mt], bh[2 * u], bh[2 * u + 1]);
                    }
                }
            }
        }
    };

    issue_stage(0, 0);
    issue_stage(1, 1);
    for (int t = 0; t < nchunk; t++) {
        if (t + 2 < nchunk) { CP_WAIT1(); } else { CP_WAIT0(); }
        __syncthreads();
        compute_stage(t & 1);
        __syncthreads();
        if (t + 2 < nchunk) issue_stage(t + 2, t & 1);
    }

#pragma unroll
    for (int mt = 0; mt < 2; mt++) {
#pragma unroll
        for (int nt = 0; nt < 8; nt++) {
            const int r  = row0 + wm * 32 + mt * 16 + (lane >> 2);
            const int cc = col0 + wn * 64 + nt * 8 + (lane & 3) * 2;
            if (OUTMODE == 0) {
                float* p = Cf + (size_t)r * DMODEL + cc;
                *(float2*)p = make_float2(acc[mt][nt][0], acc[mt][nt][1]);
                *(float2*)(p + 8 * DMODEL) = make_float2(acc[mt][nt][2], acc[mt][nt][3]);
            } else {
                __nv_bfloat16 h0, h1, l0, l1;
                split2(acc[mt][nt][0], h0, l0);
                split2(acc[mt][nt][1], h1, l1);
                *(__nv_bfloat162*)(Chi + (size_t)r * DMODEL + cc) = __nv_bfloat162(h0, h1);
                *(__nv_bfloat162*)(Clo + (size_t)r * DMODEL + cc) = __nv_bfloat162(l0, l1);
                split2(acc[mt][nt][2], h0, l0);
                split2(acc[mt][nt][3], h1, l1);
                *(__nv_bfloat162*)(Chi + (size_t)(r + 8) * DMODEL + cc) = __nv_bfloat162(h0, h1);
                *(__nv_bfloat162*)(Clo + (size_t)(r + 8) * DMODEL + cc) = __nv_bfloat162(l0, l1);
            }
        }
    }
}

// QKV projections: one launch, z in {0,1,2} selects operand set
__global__ __launch_bounds__(256, 2) void gemm_qkv3(
    const __nv_bfloat16* a0h, const __nv_bfloat16* a0l,
    const __nv_bfloat16* a1h, const __nv_bfloat16* a1l,
    const __nv_bfloat16* a2h, const __nv_bfloat16* a2l,
    const __nv_bfloat16* b0h, const __nv_bfloat16* b0l,
    const __nv_bfloat16* b1h, const __nv_bfloat16* b1l,
    const __nv_bfloat16* b2h, const __nv_bfloat16* b2l,
    __nv_bfloat16* c0h, __nv_bfloat16* c0l,
    __nv_bfloat16* c1h, __nv_bfloat16* c1l,
    __nv_bfloat16* c2h, __nv_bfloat16* c2l)
{
    const int z = blockIdx.z;
    const __nv_bfloat16* Ah = (z == 0) ? a0h : ((z == 1) ? a1h : a2h);
    const __nv_bfloat16* Al = (z == 0) ? a0l : ((z == 1) ? a1l : a2l);
    const __nv_bfloat16* Bh = (z == 0) ? b0h : ((z == 1) ? b1h : b2h);
    const __nv_bfloat16* Bl = (z == 0) ? b0l : ((z == 1) ? b1l : b2l);
    __nv_bfloat16* Ch = (z == 0) ? c0h : ((z == 1) ? c1h : c2h);
    __nv_bfloat16* Cl = (z == 0) ? c0l : ((z == 1) ? c1l : c2l);
    gemm_body<1>(Ah, Al, Bh, Bl, nullptr, Ch, Cl);
}

// Output projection
__global__ __launch_bounds__(256, 2) void gemm_wo(
    const __nv_bfloat16* Ah, const __nv_bfloat16* Al,
    const __nv_bfloat16* Bh, const __nv_bfloat16* Bl, float* Cf)
{
    gemm_body<0>(Ah, Al, Bh, Bl, Cf, nullptr, nullptr);
}

// ===========================================================================
// fp32 -> bf16 hi/lo split, z-batched over up to 4 tensors
// ===========================================================================
__global__ __launch_bounds__(256) void split_z(
    const float* __restrict__ x0, const float* __restrict__ x1,
    const float* __restrict__ x2, const float* __restrict__ x3,
    __nv_bfloat16* __restrict__ h0, __nv_bfloat16* __restrict__ l0,
    __nv_bfloat16* __restrict__ h1, __nv_bfloat16* __restrict__ l1,
    __nv_bfloat16* __restrict__ h2, __nv_bfloat16* __restrict__ l2,
    __nv_bfloat16* __restrict__ h3, __nv_bfloat16* __restrict__ l3,
    int n4)
{
    const int z = blockIdx.y;
    const float* x = (z == 0) ? x0 : ((z == 1) ? x1 : ((z == 2) ? x2 : x3));
    __nv_bfloat16* hi = (z == 0) ? h0 : ((z == 1) ? h1 : ((z == 2) ? h2 : h3));
    __nv_bfloat16* lo = (z == 0) ? l0 : ((z == 1) ? l1 : ((z == 2) ? l2 : l3));
    int i = blockIdx.x * 256 + threadIdx.x;
    if (i >= n4) return;
    float4 v = ((const float4*)x)[i];
    __nv_bfloat16 a0, a1, a2, a3, b0, b1, b2, b3;
    split2(v.x, a0, b0); split2(v.y, a1, b1);
    split2(v.z, a2, b2); split2(v.w, a3, b3);
    ((__nv_bfloat162*)hi)[2 * i + 0] = __nv_bfloat162(a0, a1);
    ((__nv_bfloat162*)hi)[2 * i + 1] = __nv_bfloat162(a2, a3);
    ((__nv_bfloat162*)lo)[2 * i + 0] = __nv_bfloat162(b0, b1);
    ((__nv_bfloat162*)lo)[2 * i + 1] = __nv_bfloat162(b2, b3);
}

// ===========================================================================
// Fused flash attention (unchanged from Round 7)
// ===========================================================================
#define FA_LDSB    272
#define FA_QTILE   (128 * FA_LDSB)
#define FA_KVTILE  (64 * FA_LDSB)
#define FA_STG     (4 * FA_KVTILE)
#define FA_SMEM    (2 * FA_QTILE + 2 * FA_STG)  // 208896

__global__ __launch_bounds__(256, 1) void fused_attn(
    const __nv_bfloat16* __restrict__ Qhi, const __nv_bfloat16* __restrict__ Qlo,
    const __nv_bfloat16* __restrict__ Khi, const __nv_bfloat16* __restrict__ Klo,
    const __nv_bfloat16* __restrict__ Vhi, const __nv_bfloat16* __restrict__ Vlo,
    __nv_bfloat16* __restrict__ Ohi, __nv_bfloat16* __restrict__ Olo)
{
    extern __shared__ char smem[];
    const uint32_t sb = smem_u32(smem);
    const int tid  = threadIdx.x;
    const int lane = tid & 31, wid = tid >> 5;
    const int qrow0 = blockIdx.x * 128;
    const int z  = blockIdx.y;
    const int bb = z >> 4, hh = z & 15;
    const size_t base = (size_t)bb * S_LEN * DMODEL + (size_t)hh * DK;

    const __nv_bfloat16* qsrc[2] = {Qhi + base, Qlo + base};
    const __nv_bfloat16* kvsrc[4] = {Khi + base, Klo + base, Vhi + base, Vlo + base};

    const uint32_t sQ = sb;
    const uint32_t sKV = sb + 2 * FA_QTILE;

#pragma unroll
    for (int i = 0; i < 16; i++) {
        const int c = tid + i * 256;
        const int t = c >> 11, rem = c & 2047;
        const int r = rem >> 4, q = rem & 15;
        CP_ASYNC16(sQ + t * FA_QTILE + r * FA_LDSB + q * 16,
                   qsrc[t] + (size_t)(qrow0 + r) * DMODEL + q * 8);
    }
    auto issue_stage = [&](int j, int s) {
        const int s0 = j << 6;
        const uint32_t sbase = sKV + s * FA_STG;
#pragma unroll
        for (int i = 0; i < 16; i++) {
            const int c = tid + i * 256;
            const int t = c >> 10, rem = c & 1023;
            const int r = rem >> 4, q = rem & 15;
            CP_ASYNC16(sbase + t * FA_KVTILE + r * FA_LDSB + q * 16,
                       kvsrc[t] + (size_t)(s0 + r) * DMODEL + q * 8);
        }
        CP_COMMIT();
    };
    issue_stage(0, 0);
    issue_stage(1, 1);

    float accO[16][4];
#pragma unroll
    for (int nt = 0; nt < 16; nt++)
#pragma unroll
        for (int r = 0; r < 4; r++) accO[nt][r] = 0.0f;
    float mrow[2] = {-1e30f, -1e30f};
    float lrow[2] = {0.0f, 0.0f};
    const float csc = 0.08838834764831845f;

    const int arow  = wid * 16 + (lane & 15);
    const int acolb = (lane >> 4) * 16;
    const int brow  = (lane & 7) + ((lane >> 4) & 1) * 8;
    const int bcolb = ((lane >> 3) & 1) * 16;
    const int btr   = (lane & 7) + ((lane >> 3) & 1) * 8;
    const int btc   = ((lane >> 4) & 1) * 8;

    const int NITER = S_LEN / 64;
    for (int j = 0; j < NITER; j++) {
        if (j + 2 < NITER) { CP_WAIT1(); } else { CP_WAIT0(); }
        __syncthreads();
        const uint32_t st = sKV + (j & 1) * FA_STG;
        const uint32_t sKh = st;
        const uint32_t sKl = st + FA_KVTILE;
        const uint32_t sVh = st + 2 * FA_KVTILE;
        const uint32_t sVl = st + 3 * FA_KVTILE;

        float sacc[8][4];
#pragma unroll
        for (int nt = 0; nt < 8; nt++)
#pragma unroll
            for (int r = 0; r < 4; r++) sacc[nt][r] = 0.0f;

#pragma unroll
        for (int kst = 0; kst < 8; kst++) {
            const int kb = kst * 32;
            uint32_t qh[4], ql[4];
            LDSM_X4(qh[0], qh[1], qh[2], qh[3], sQ + arow * FA_LDSB + acolb + kb);
            LDSM_X4(ql[0], ql[1], ql[2], ql[3], sQ + FA_QTILE + arow * FA_LDSB + acolb + kb);
#pragma unroll
            for (int np = 0; np < 4; np++) {
                const uint32_t bo = (uint32_t)(brow + np * 16) * FA_LDSB + bcolb + kb;
                uint32_t kh[4], kl[4];
                LDSM_X4(kh[0], kh[1], kh[2], kh[3], sKh + bo);
                LDSM_X4(kl[0], kl[1], kl[2], kl[3], sKl + bo);
#pragma unroll
                for (int u = 0; u < 2; u++) {
                    float* c = sacc[np * 2 + u];
                    MMA_BF16(c, qh, kh[2 * u], kh[2 * u + 1]);
                    MMA_BF16(c, qh, kl[2 * u], kl[2 * u + 1]);
                    MMA_BF16(c, ql, kh[2 * u], kh[2 * u + 1]);
                }
            }
        }

        float mnew[2] = {mrow[0], mrow[1]};
#pragma unroll
        for (int nt = 0; nt < 8; nt++) {
            mnew[0] = fmaxf(mnew[0], fmaxf(sacc[nt][0], sacc[nt][1]));
            mnew[1] = fmaxf(mnew[1], fmaxf(sacc[nt][2], sacc[nt][3]));
        }
#pragma unroll
        for (int o = 1; o <= 2; o <<= 1) {
            mnew[0] = fmaxf(mnew[0], __shfl_xor_sync(0xffffffffu, mnew[0], o));
            mnew[1] = fmaxf(mnew[1], __shfl_xor_sync(0xffffffffu, mnew[1], o));
        }
        const float sc0 = __expf((mrow[0] - mnew[0]) * csc);
        const float sc1 = __expf((mrow[1] - mnew[1]) * csc);
        mrow[0] = mnew[0]; mrow[1] = mnew[1];
        lrow[0] *= sc0; lrow[1] *= sc1;
#pragma unroll
        for (int nt = 0; nt < 16; nt++) {
            accO[nt][0] *= sc0; accO[nt][1] *= sc0;
            accO[nt][2] *= sc1; accO[nt][3] *= sc1;
        }

        uint32_t ph[4][4], pl[4][4];
        float ls0 = 0.0f, ls1 = 0.0f;
#pragma unroll
        for (int t2 = 0; t2 < 4; t2++) {
#pragma unroll
            for (int half = 0; half < 2; half++) {
                float* s = sacc[2 * t2 + half];
                float p0 = __expf((s[0] - mnew[0]) * csc);
                float p1 = __expf((s[1] - mnew[0]) * csc);
                float p2 = __expf((s[2] - mnew[1]) * csc);
                float p3 = __expf((s[3] - mnew[1]) * csc);
                ls0 += p0 + p1; ls1 += p2 + p3;
                __nv_bfloat16 h0, h1, h2, h3, l0, l1, l2, l3;
                split2(p0, h0, l0); split2(p1, h1, l1);
                split2(p2, h2, l2); split2(p3, h3, l3);
                ph[t2][2 * half + 0] = packb(h0, h1);
                ph[t2][2 * half + 1] = packb(h2, h3);
                pl[t2][2 * half + 0] = packb(l0, l1);
                pl[t2][2 * half + 1] = packb(l2, l3);
            }
        }
        lrow[0] += ls0; lrow[1] += ls1;

#pragma unroll
        for (int t2 = 0; t2 < 4; t2++) {
#pragma unroll
            for (int np = 0; np < 8; np++) {
                const uint32_t bo = (uint32_t)(t2 * 16 + btr) * FA_LDSB + (np * 16 + btc) * 2;
                uint32_t vh[4], vl[4];
                LDSM_X4_T(vh[0], vh[1], vh[2], vh[3], sVh + bo);
                LDSM_X4_T(vl[0], vl[1], vl[2], vl[3], sVl + bo);
#pragma unroll
                for (int u = 0; u < 2; u++) {
                    float* c = accO[np * 2 + u];
                    MMA_BF16(c, ph[t2], vh[2 * u], vh[2 * u + 1]);
                    MMA_BF16(c, ph[t2], vl[2 * u], vl[2 * u + 1]);
                    MMA_BF16(c, pl[t2], vh[2 * u], vh[2 * u + 1]);
                }
            }
        }

        __syncthreads();
        if (j + 2 < NITER) issue_stage(j + 2, j & 1);
    }

#pragma unroll
    for (int o = 1; o <= 2; o <<= 1) {
        lrow[0] += __shfl_xor_sync(0xffffffffu, lrow[0], o);
        lrow[1] += __shfl_xor_sync(0xffffffffu, lrow[1], o);
    }
    const float inv0 = 1.0f / lrow[0];
    const float inv1 = 1.0f / lrow[1];
    const int r0 = qrow0 + wid * 16 + (lane >> 2);
#pragma unroll
    for (int nt = 0; nt < 16; nt++) {
        const int cc = nt * 8 + (lane & 3) * 2;
        __nv_bfloat16 h0, h1, l0, l1;
        split2(accO[nt][0] * inv0, h0, l0);
        split2(accO[nt][1] * inv0, h1, l1);
        *(__nv_bfloat162*)(Ohi + base + (size_t)r0 * DMODEL + cc) = __nv_bfloat162(h0, h1);
        *(__nv_bfloat162*)(Olo + base + (size_t)r0 * DMODEL + cc) = __nv_bfloat162(l0, l1);
        split2(accO[nt][2] * inv1, h0, l0);
        split2(accO[nt][3] * inv1, h1, l1);
        *(__nv_bfloat162*)(Ohi + base + (size_t)(r0 + 8) * DMODEL + cc) = __nv_bfloat162(h0, h1);
        *(__nv_bfloat162*)(Olo + base + (size_t)(r0 + 8) * DMODEL + cc) = __nv_bfloat162(l0, l1);
    }
}

// ---------------------------------------------------------------------------
extern "C" void kernel_launch(void* const* d_in, const int* in_sizes, int n_in,
                              void* d_out, int out_size)
{
    const float* q   = (const float*)d_in[0];
    const float* k   = (const float*)d_in[1];
    const float* v   = (const float*)d_in[2];
    const float* w_q = (const float*)d_in[3];
    const float* w_k = (const float*)d_in[4];
    const float* w_v = (const float*)d_in[5];
    const float* w_o = (const float*)d_in[6];
    float* out = (float*)d_out;

    __nv_bfloat16 *qhi, *qlo, *khi, *klo, *vhi, *vlo, *athi, *atlo;
    __nv_bfloat16 *xqh, *xql, *xkh, *xkl, *xvh, *xvl;
    __nv_bfloat16 *wqh, *wql, *wkh, *wkl, *wvh, *wvl, *woh, *wol;
    cudaGetSymbolAddress((void**)&qhi, g_qhi);  cudaGetSymbolAddress((void**)&qlo, g_qlo);
    cudaGetSymbolAddress((void**)&khi, g_khi);  cudaGetSymbolAddress((void**)&klo, g_klo);
    cudaGetSymbolAddress((void**)&vhi, g_vhi);  cudaGetSymbolAddress((void**)&vlo, g_vlo);
    cudaGetSymbolAddress((void**)&athi, g_athi); cudaGetSymbolAddress((void**)&atlo, g_atlo);
    cudaGetSymbolAddress((void**)&xqh, g_xqh);  cudaGetSymbolAddress((void**)&xql, g_xql);
    cudaGetSymbolAddress((void**)&xkh, g_xkh);  cudaGetSymbolAddress((void**)&xkl, g_xkl);
    cudaGetSymbolAddress((void**)&xvh, g_xvh);  cudaGetSymbolAddress((void**)&xvl, g_xvl);
    cudaGetSymbolAddress((void**)&wqh, g_wqh);  cudaGetSymbolAddress((void**)&wql, g_wql);
    cudaGetSymbolAddress((void**)&wkh, g_wkh);  cudaGetSymbolAddress((void**)&wkl, g_wkl);
    cudaGetSymbolAddress((void**)&wvh, g_wvh);  cudaGetSymbolAddress((void**)&wvl, g_wvl);
    cudaGetSymbolAddress((void**)&woh, g_woh);  cudaGetSymbolAddress((void**)&wol, g_wol);

    cudaFuncSetAttribute(gemm_qkv3, cudaFuncAttributeMaxDynamicSharedMemorySize, NT_SMEM);
    cudaFuncSetAttribute(gemm_wo, cudaFuncAttributeMaxDynamicSharedMemorySize, NT_SMEM);
    cudaFuncSetAttribute(fused_attn, cudaFuncAttributeMaxDynamicSharedMemorySize, FA_SMEM);

    const int M_rows = NBATCH * S_LEN;
    const int nact4 = (int)((size_t)M_rows * DMODEL / 4);
    const int nw4   = (int)((size_t)DMODEL * DMODEL / 4);
    dim3 blk(256);

    // 1) Split activations (z=3) and all weights (z=4)
    {
        dim3 ga((nact4 + 255) / 256, 3);
        split_z<<<ga, blk>>>(q, k, v, nullptr,
                             xqh, xql, xkh, xkl, xvh, xvl, nullptr, nullptr, nact4);
        dim3 gw((nw4 + 255) / 256, 4);
        split_z<<<gw, blk>>>(w_q, w_k, w_v, w_o,
                             wqh, wql, wkh, wkl, wvh, wvl, woh, wol, nw4);
    }

    // 2) QKV projections in one launch (z selects q/k/v)
    {
        dim3 grid(DMODEL / 128, M_rows / 128, 3);
        gemm_qkv3<<<grid, blk, NT_SMEM>>>(
            xqh, xql, xkh, xkl, xvh, xvl,
            wqh, wql, wkh, wkl, wvh, wvl,
            qhi, qlo, khi, klo, vhi, vlo);
    }

    // 3) Fused attention
    {
        dim3 grid(S_LEN / 128, NBATCH * NHEADS);
        fused_attn<<<grid, blk, FA_SMEM>>>(qhi, qlo, khi, klo, vhi, vlo, athi, atlo);
    }

    // 4) Output projection -> fp32 d_out
    {
        dim3 grid(DMODEL / 128, M_rows / 128);
        gemm_wo<<<grid, blk, NT_SMEM>>>(athi, atlo, woh, wol, out);
    }
}

// round 10
// speedup vs baseline: 1.6238x; 1.4736x over previous
#include <cuda_runtime.h>
#include <cuda_fp16.h>
#include <math.h>
#include <stdint.h>

#define S_LEN   2048
#define DMODEL  2048
#define NHEADS  16
#define DK      128
#define NBATCH  4

// ---------------- static device scratch (fp16) ------------------------------
__device__ __half g_qhi[(size_t)NBATCH * S_LEN * DMODEL];
__device__ __half g_qlo[(size_t)NBATCH * S_LEN * DMODEL];
__device__ __half g_k16[(size_t)NBATCH * S_LEN * DMODEL];
__device__ __half g_v16[(size_t)NBATCH * S_LEN * DMODEL];
__device__ __half g_athi[(size_t)NBATCH * S_LEN * DMODEL];
__device__ __half g_atlo[(size_t)NBATCH * S_LEN * DMODEL];
// split activations (A operands of QKV projections)
__device__ __half g_xqh[(size_t)NBATCH * S_LEN * DMODEL];
__device__ __half g_xql[(size_t)NBATCH * S_LEN * DMODEL];
__device__ __half g_xkh[(size_t)NBATCH * S_LEN * DMODEL];
__device__ __half g_xkl[(size_t)NBATCH * S_LEN * DMODEL];
__device__ __half g_xvh[(size_t)NBATCH * S_LEN * DMODEL];
__device__ __half g_xvl[(size_t)NBATCH * S_LEN * DMODEL];
// weights rounded to single fp16 (B operands)
__device__ __half g_wq16[(size_t)DMODEL * DMODEL];
__device__ __half g_wk16[(size_t)DMODEL * DMODEL];
__device__ __half g_wv16[(size_t)DMODEL * DMODEL];
__device__ __half g_wo16[(size_t)DMODEL * DMODEL];

// ======================= PTX helpers =======================================
__device__ __forceinline__ uint32_t smem_u32(const void* p) {
    uint32_t a;
    asm("{ .reg .u64 t; cvta.to.shared.u64 t, %1; cvt.u32.u64 %0, t; }" : "=r"(a) : "l"(p));
    return a;
}
#define CP_ASYNC16(dst, src) asm volatile("cp.async.cg.shared.global [%0], [%1], 16;" :: "r"(dst), "l"(src))
#define CP_COMMIT()          asm volatile("cp.async.commit_group;" ::: "memory")
#define CP_WAIT0()           asm volatile("cp.async.wait_group 0;" ::: "memory")
#define CP_WAIT1()           asm volatile("cp.async.wait_group 1;" ::: "memory")

#define LDSM_X4(r0, r1, r2, r3, addr) \
    asm volatile("ldmatrix.sync.aligned.m8n8.x4.shared.b16 {%0,%1,%2,%3}, [%4];" \
        : "=r"(r0), "=r"(r1), "=r"(r2), "=r"(r3) : "r"(addr))
#define LDSM_X4_T(r0, r1, r2, r3, addr) \
    asm volatile("ldmatrix.sync.aligned.m8n8.x4.trans.shared.b16 {%0,%1,%2,%3}, [%4];" \
        : "=r"(r0), "=r"(r1), "=r"(r2), "=r"(r3) : "r"(addr))

#define MMA_F16(c, a, b0, b1) \
    asm volatile("mma.sync.aligned.m16n8k16.row.col.f32.f16.f16.f32 " \
        "{%0,%1,%2,%3},{%4,%5,%6,%7},{%8,%9},{%0,%1,%2,%3};" \
        : "+f"((c)[0]), "+f"((c)[1]), "+f"((c)[2]), "+f"((c)[3]) \
        : "r"((a)[0]), "r"((a)[1]), "r"((a)[2]), "r"((a)[3]), "r"(b0), "r"(b1))

__device__ __forceinline__ void split2h(float x, __half& h, __half& l) {
    h = __float2half_rn(x);
    l = __float2half_rn(x - __half2float(h));
}
__device__ __forceinline__ uint32_t packh(__half a, __half b) {
    __half2 t = __halves2half2(a, b);
    return *(uint32_t*)&t;
}

// ===========================================================================
// fp16 2-pass NT GEMM: C[m,n] = sum_k (Ahi+Alo)[m,k] * B16[n,k]
// Block 128x128, BK=32, 256 threads (8 warps 4m x 2n), double buffer.
// outmode: 0 = fp32 C, 1 = split half hi/lo C, 2 = single half C
// ===========================================================================
#define LDSB 80
#define ARR_BYTES (128 * LDSB)      // 10240
#define PSTG (3 * ARR_BYTES)        // 30720 (Ahi, Alo, B)
#define NT_SMEM (2 * PSTG)          // 61440

__device__ __forceinline__ void gemm_body(
    const __half* __restrict__ Ahi, const __half* __restrict__ Alo,
    const __half* __restrict__ B16,
    float* __restrict__ Cf, __half* __restrict__ Chh, __half* __restrict__ Chl,
    __half* __restrict__ C16, int outmode)
{
    extern __shared__ char smem[];
    const uint32_t sb = smem_u32(smem);
    const int tid  = threadIdx.x;
    const int lane = tid & 31, wid = tid >> 5;
    const int wm   = wid & 3, wn = wid >> 2;
    const int row0 = blockIdx.y * 128;
    const int col0 = blockIdx.x * 128;

    const __half* gsrc[3] = {Ahi, Alo, B16};
    const int nchunk = DMODEL >> 5;   // 64

    auto issue_stage = [&](int kt, int s) {
        const int k0 = kt << 5;
        const uint32_t sbase = sb + s * PSTG;
#pragma unroll
        for (int a = 0; a < 3; a++) {
            const __half* g = gsrc[a];
            const int rbase = (a < 2) ? row0 : col0;
#pragma unroll
            for (int i = 0; i < 2; i++) {
                const int c = tid + i * 256;
                const int r = c >> 2, q = c & 3;
                CP_ASYNC16(sbase + a * ARR_BYTES + r * LDSB + q * 16,
                           g + (size_t)(rbase + r) * DMODEL + k0 + q * 8);
            }
        }
        CP_COMMIT();
    };

    float acc[2][8][4];
#pragma unroll
    for (int mt = 0; mt < 2; mt++)
#pragma unroll
        for (int nt = 0; nt < 8; nt++)
#pragma unroll
            for (int r = 0; r < 4; r++) acc[mt][nt][r] = 0.0f;

    const int arow  = wm * 32 + (lane & 15);
    const int acolb = ((lane >> 4) << 3) * 2;
    const int brow  = wn * 64 + (lane & 7) + ((lane >> 4) & 1) * 8;
    const int bcolb = (((lane >> 3) & 1) << 3) * 2;

    auto compute_stage = [&](int s) {
        const uint32_t sbase = sb + s * PSTG;
        const uint32_t sAhi = sbase;
        const uint32_t sAlo = sbase + ARR_BYTES;
        const uint32_t sB   = sbase + 2 * ARR_BYTES;
#pragma unroll
        for (int h = 0; h < 2; h++) {
            const int kb = h * 32;
            uint32_t ah[2][4], al[2][4];
            {
                uint32_t a0 = sAhi + arow * LDSB + acolb + kb;
                LDSM_X4(ah[0][0], ah[0][1], ah[0][2], ah[0][3], a0);
                LDSM_X4(ah[1][0], ah[1][1], ah[1][2], ah[1][3], a0 + 16 * LDSB);
                uint32_t l0 = sAlo + arow * LDSB + acolb + kb;
                LDSM_X4(al[0][0], al[0][1], al[0][2], al[0][3], l0);
                LDSM_X4(al[1][0], al[1][1], al[1][2], al[1][3], l0 + 16 * LDSB);
            }
#pragma unroll
            for (int np = 0; np < 4; np++) {
                uint32_t bq[4];
                const uint32_t bo = (brow + np * 16) * LDSB + bcolb + kb;
                LDSM_X4(bq[0], bq[1], bq[2], bq[3], sB + bo);
#pragma unroll
                for (int mt = 0; mt < 2; mt++) {
#pragma unroll
                    for (int u = 0; u < 2; u++) {
                        float* c = acc[mt][np * 2 + u];
                        MMA_F16(c, ah[mt], bq[2 * u], bq[2 * u + 1]);
                        MMA_F16(c, al[mt], bq[2 * u], bq[2 * u + 1]);
                    }
                }
            }
        }
    };

    issue_stage(0, 0);
    issue_stage(1, 1);
    for (int t = 0; t < nchunk; t++) {
        if (t + 2 < nchunk) { CP_WAIT1(); } else { CP_WAIT0(); }
        __syncthreads();
        compute_stage(t & 1);
        __syncthreads();
        if (t + 2 < nchunk) issue_stage(t + 2, t & 1);
    }

#pragma unroll
    for (int mt = 0; mt < 2; mt++) {
#pragma unroll
        for (int nt = 0; nt < 8; nt++) {
            const int r  = row0 + wm * 32 + mt * 16 + (lane >> 2);
            const int cc = col0 + wn * 64 + nt * 8 + (lane & 3) * 2;
            if (outmode == 0) {
                float* p = Cf + (size_t)r * DMODEL + cc;
                *(float2*)p = make_float2(acc[mt][nt][0], acc[mt][nt][1]);
                *(float2*)(p + 8 * DMODEL) = make_float2(acc[mt][nt][2], acc[mt][nt][3]);
            } else if (outmode == 1) {
                __half h0, h1, l0, l1;
                split2h(acc[mt][nt][0], h0, l0);
                split2h(acc[mt][nt][1], h1, l1);
                *(__half2*)(Chh + (size_t)r * DMODEL + cc) = __halves2half2(h0, h1);
                *(__half2*)(Chl + (size_t)r * DMODEL + cc) = __halves2half2(l0, l1);
                split2h(acc[mt][nt][2], h0, l0);
                split2h(acc[mt][nt][3], h1, l1);
                *(__half2*)(Chh + (size_t)(r + 8) * DMODEL + cc) = __halves2half2(h0, h1);
                *(__half2*)(Chl + (size_t)(r + 8) * DMODEL + cc) = __halves2half2(l0, l1);
            } else {
                *(__half2*)(C16 + (size_t)r * DMODEL + cc) =
                    __halves2half2(__float2half_rn(acc[mt][nt][0]), __float2half_rn(acc[mt][nt][1]));
                *(__half2*)(C16 + (size_t)(r + 8) * DMODEL + cc) =
                    __halves2half2(__float2half_rn(acc[mt][nt][2]), __float2half_rn(acc[mt][nt][3]));
            }
        }
    }
}

// QKV projections: z=0 -> Q (split out), z=1 -> K (half out), z=2 -> V (half out)
__global__ __launch_bounds__(256, 2) void gemm_qkv3(
    const __half* a0h, const __half* a0l,
    const __half* a1h, const __half* a1l,
    const __half* a2h, const __half* a2l,
    const __half* b0, const __half* b1, const __half* b2,
    __half* qh, __half* ql, __half* k16, __half* v16)
{
    const int z = blockIdx.z;
    const __half* Ah = (z == 0) ? a0h : ((z == 1) ? a1h : a2h);
    const __half* Al = (z == 0) ? a0l : ((z == 1) ? a1l : a2l);
    const __half* B  = (z == 0) ? b0 : ((z == 1) ? b1 : b2);
    if (z == 0) gemm_body(Ah, Al, B, nullptr, qh, ql, nullptr, 1);
    else        gemm_body(Ah, Al, B, nullptr, nullptr, nullptr, (z == 1) ? k16 : v16, 2);
}

__global__ __launch_bounds__(256, 2) void gemm_wo(
    const __half* Ah, const __half* Al, const __half* B, float* Cf)
{
    gemm_body(Ah, Al, B, Cf, nullptr, nullptr, nullptr, 0);
}

// ===========================================================================
// fp32 -> fp16 hi/lo split (activations), z-batched over 3 tensors
// ===========================================================================
__global__ __launch_bounds__(256) void split_h3(
    const float* __restrict__ x0, const float* __restrict__ x1, const float* __restrict__ x2,
    __half* __restrict__ h0, __half* __restrict__ l0,
    __half* __restrict__ h1, __half* __restrict__ l1,
    __half* __restrict__ h2, __half* __restrict__ l2, int n4)
{
    const int z = blockIdx.y;
    const float* x = (z == 0) ? x0 : ((z == 1) ? x1 : x2);
    __half* hi = (z == 0) ? h0 : ((z == 1) ? h1 : h2);
    __half* lo = (z == 0) ? l0 : ((z == 1) ? l1 : l2);
    int i = blockIdx.x * 256 + threadIdx.x;
    if (i >= n4) return;
    float4 v = ((const float4*)x)[i];
    __half a0, a1, a2, a3, b0, b1, b2, b3;
    split2h(v.x, a0, b0); split2h(v.y, a1, b1);
    split2h(v.z, a2, b2); split2h(v.w, a3, b3);
    ((__half2*)hi)[2 * i + 0] = __halves2half2(a0, a1);
    ((__half2*)hi)[2 * i + 1] = __halves2half2(a2, a3);
    ((__half2*)lo)[2 * i + 0] = __halves2half2(b0, b1);
    ((__half2*)lo)[2 * i + 1] = __halves2half2(b2, b3);
}

// fp32 -> single fp16 (weights), z-batched over 4 tensors
__global__ __launch_bounds__(256) void conv_h4(
    const float* __restrict__ x0, const float* __restrict__ x1,
    const float* __restrict__ x2, const float* __restrict__ x3,
    __half* __restrict__ y0, __half* __restrict__ y1,
    __half* __restrict__ y2, __half* __restrict__ y3, int n4)
{
    const int z = blockIdx.y;
    const float* x = (z == 0) ? x0 : ((z == 1) ? x1 : ((z == 2) ? x2 : x3));
    __half* y = (z == 0) ? y0 : ((z == 1) ? y1 : ((z == 2) ? y2 : y3));
    int i = blockIdx.x * 256 + threadIdx.x;
    if (i >= n4) return;
    float4 v = ((const float4*)x)[i];
    ((__half2*)y)[2 * i + 0] = __halves2half2(__float2half_rn(v.x), __float2half_rn(v.y));
    ((__half2*)y)[2 * i + 1] = __halves2half2(__float2half_rn(v.z), __float2half_rn(v.w));
}

// ===========================================================================
// Fused flash attention, fp16 2-pass:
//   S = (Qhi+Qlo) K^T ; online softmax ; O += (Phi+Plo) V
// Q hi/lo persistent in smem; K,V single fp16 per 64-row block, 2-stage.
// ===========================================================================
#define FA_LDSB    272
#define FA_QTILE   (128 * FA_LDSB)              // 34816
#define FA_KVTILE  (64 * FA_LDSB)               // 17408
#define FA_KVSTG   (2 * FA_KVTILE)              // 34816 (K + V)
#define FA_SMEM    (2 * FA_QTILE + 2 * FA_KVSTG) // 139264

__global__ __launch_bounds__(256, 1) void fused_attn(
    const __half* __restrict__ Qhi, const __half* __restrict__ Qlo,
    const __half* __restrict__ K16, const __half* __restrict__ V16,
    __half* __restrict__ Ohi, __half* __restrict__ Olo)
{
    extern __shared__ char smem[];
    const uint32_t sb = smem_u32(smem);
    const int tid  = threadIdx.x;
    const int lane = tid & 31, wid = tid >> 5;
    const int qrow0 = blockIdx.x * 128;
    const int z  = blockIdx.y;
    const int bb = z >> 4, hh = z & 15;
    const size_t base = (size_t)bb * S_LEN * DMODEL + (size_t)hh * DK;

    const __half* qsrc[2] = {Qhi + base, Qlo + base};
    const __half* kvsrc[2] = {K16 + base, V16 + base};

    const uint32_t sQ = sb;
    const uint32_t sKV = sb + 2 * FA_QTILE;

#pragma unroll
    for (int i = 0; i < 16; i++) {
        const int c = tid + i * 256;
        const int t = c >> 11, rem = c & 2047;
        const int r = rem >> 4, q = rem & 15;
        CP_ASYNC16(sQ + t * FA_QTILE + r * FA_LDSB + q * 16,
                   qsrc[t] + (size_t)(qrow0 + r) * DMODEL + q * 8);
    }
    auto issue_stage = [&](int j, int s) {
        const int s0 = j << 6;
        const uint32_t sbase = sKV + s * FA_KVSTG;
#pragma unroll
        for (int i = 0; i < 8; i++) {
            const int c = tid + i * 256;                 // 0..2047
            const int t = c >> 10, rem = c & 1023;
            const int r = rem >> 4, q = rem & 15;
            CP_ASYNC16(sbase + t * FA_KVTILE + r * FA_LDSB + q * 16,
                       kvsrc[t] + (size_t)(s0 + r) * DMODEL + q * 8);
        }
        CP_COMMIT();
    };
    issue_stage(0, 0);
    issue_stage(1, 1);

    float accO[16][4];
#pragma unroll
    for (int nt = 0; nt < 16; nt++)
#pragma unroll
        for (int r = 0; r < 4; r++) accO[nt][r] = 0.0f;
    float mrow[2] = {-1e30f, -1e30f};
    float lrow[2] = {0.0f, 0.0f};
    const float csc = 0.08838834764831845f;

    const int arow  = wid * 16 + (lane & 15);
    const int acolb = (lane >> 4) * 16;
    const int brow  = (lane & 7) + ((lane >> 4) & 1) * 8;
    const int bcolb = ((lane >> 3) & 1) * 16;
    const int btr   = (lane & 7) + ((lane >> 3) & 1) * 8;
    const int btc   = ((lane >> 4) & 1) * 8;

    const int NITER = S_LEN / 64;
    for (int j = 0; j < NITER; j++) {
        if (j + 2 < NITER) { CP_WAIT1(); } else { CP_WAIT0(); }
        __syncthreads();
        const uint32_t st = sKV + (j & 1) * FA_KVSTG;
        const uint32_t sK = st;
        const uint32_t sV = st + FA_KVTILE;

        float sacc[8][4];
#pragma unroll
        for (int nt = 0; nt < 8; nt++)
#pragma unroll
            for (int r = 0; r < 4; r++) sacc[nt][r] = 0.0f;

#pragma unroll
        for (int kst = 0; kst < 8; kst++) {
            const int kb = kst * 32;
            uint32_t qh[4], ql[4];
            LDSM_X4(qh[0], qh[1], qh[2], qh[3], sQ + arow * FA_LDSB + acolb + kb);
            LDSM_X4(ql[0], ql[1], ql[2], ql[3], sQ + FA_QTILE + arow * FA_LDSB + acolb + kb);
#pragma unroll
            for (int np = 0; np < 4; np++) {
                const uint32_t bo = (uint32_t)(brow + np * 16) * FA_LDSB + bcolb + kb;
                uint32_t kq[4];
                LDSM_X4(kq[0], kq[1], kq[2], kq[3], sK + bo);
#pragma unroll
                for (int u = 0; u < 2; u++) {
                    float* c = sacc[np * 2 + u];
                    MMA_F16(c, qh, kq[2 * u], kq[2 * u + 1]);
                    MMA_F16(c, ql, kq[2 * u], kq[2 * u + 1]);
                }
            }
        }

        float mnew[2] = {mrow[0], mrow[1]};
#pragma unroll
        for (int nt = 0; nt < 8; nt++) {
            mnew[0] = fmaxf(mnew[0], fmaxf(sacc[nt][0], sacc[nt][1]));
            mnew[1] = fmaxf(mnew[1], fmaxf(sacc[nt][2], sacc[nt][3]));
        }
#pragma unroll
        for (int o = 1; o <= 2; o <<= 1) {
            mnew[0] = fmaxf(mnew[0], __shfl_xor_sync(0xffffffffu, mnew[0], o));
            mnew[1] = fmaxf(mnew[1], __shfl_xor_sync(0xffffffffu, mnew[1], o));
        }
        const float sc0 = __expf((mrow[0] - mnew[0]) * csc);
        const float sc1 = __expf((mrow[1] - mnew[1]) * csc);
        mrow[0] = mnew[0]; mrow[1] = mnew[1];
        lrow[0] *= sc0; lrow[1] *= sc1;
#pragma unroll
        for (int nt = 0; nt < 16; nt++) {
            accO[nt][0] *= sc0; accO[nt][1] *= sc0;
            accO[nt][2] *= sc1; accO[nt][3] *= sc1;
        }

        uint32_t ph[4][4], pl[4][4];
        float ls0 = 0.0f, ls1 = 0.0f;
#pragma unroll
        for (int t2 = 0; t2 < 4; t2++) {
#pragma unroll
            for (int half = 0; half < 2; half++) {
                float* s = sacc[2 * t2 + half];
                float p0 = __expf((s[0] - mnew[0]) * csc);
                float p1 = __expf((s[1] - mnew[0]) * csc);
                float p2 = __expf((s[2] - mnew[1]) * csc);
                float p3 = __expf((s[3] - mnew[1]) * csc);
                ls0 += p0 + p1; ls1 += p2 + p3;
                __half h0, h1, h2, h3, l0, l1, l2, l3;
                split2h(p0, h0, l0); split2h(p1, h1, l1);
                split2h(p2, h2, l2); split2h(p3, h3, l3);
                ph[t2][2 * half + 0] = packh(h0, h1);
                ph[t2][2 * half + 1] = packh(h2, h3);
                pl[t2][2 * half + 0] = packh(l0, l1);
                pl[t2][2 * half + 1] = packh(l2, l3);
            }
        }
        lrow[0] += ls0; lrow[1] += ls1;

#pragma unroll
        for (int t2 = 0; t2 < 4; t2++) {
#pragma unroll
            for (int np = 0; np < 8; np++) {
                const uint32_t bo = (uint32_t)(t2 * 16 + btr) * FA_LDSB + (np * 16 + btc) * 2;
                uint32_t vq[4];
                LDSM_X4_T(vq[0], vq[1], vq[2], vq[3], sV + bo);
#pragma unroll
                for (int u = 0; u < 2; u++) {
                    float* c = accO[np * 2 + u];
                    MMA_F16(c, ph[t2], vq[2 * u], vq[2 * u + 1]);
                    MMA_F16(c, pl[t2], vq[2 * u], vq[2 * u + 1]);
                }
            }
        }

        __syncthreads();
        if (j + 2 < NITER) issue_stage(j + 2, j & 1);
    }

#pragma unroll
    for (int o = 1; o <= 2; o <<= 1) {
        lrow[0] += __shfl_xor_sync(0xffffffffu, lrow[0], o);
        lrow[1] += __shfl_xor_sync(0xffffffffu, lrow[1], o);
    }
    const float inv0 = 1.0f / lrow[0];
    const float inv1 = 1.0f / lrow[1];
    const int r0 = qrow0 + wid * 16 + (lane >> 2);
#pragma unroll
    for (int nt = 0; nt < 16; nt++) {
        const int cc = nt * 8 + (lane & 3) * 2;
        __half h0, h1, l0, l1;
        split2h(accO[nt][0] * inv0, h0, l0);
        split2h(accO[nt][1] * inv0, h1, l1);
        *(__half2*)(Ohi + base + (size_t)r0 * DMODEL + cc) = __halves2half2(h0, h1);
        *(__half2*)(Olo + base + (size_t)r0 * DMODEL + cc) = __halves2half2(l0, l1);
        split2h(accO[nt][2] * inv1, h0, l0);
        split2h(accO[nt][3] * inv1, h1, l1);
        *(__half2*)(Ohi + base + (size_t)(r0 + 8) * DMODEL + cc) = __halves2half2(h0, h1);
        *(__half2*)(Olo + base + (size_t)(r0 + 8) * DMODEL + cc) = __halves2half2(l0, l1);
    }
}

// ---------------------------------------------------------------------------
extern "C" void kernel_launch(void* const* d_in, const int* in_sizes, int n_in,
                              void* d_out, int out_size)
{
    const float* q   = (const float*)d_in[0];
    const float* k   = (const float*)d_in[1];
    const float* v   = (const float*)d_in[2];
    const float* w_q = (const float*)d_in[3];
    const float* w_k = (const float*)d_in[4];
    const float* w_v = (const float*)d_in[5];
    const float* w_o = (const float*)d_in[6];
    float* out = (float*)d_out;

    __half *qhi, *qlo, *k16, *v16, *athi, *atlo;
    __half *xqh, *xql, *xkh, *xkl, *xvh, *xvl;
    __half *wq16, *wk16, *wv16, *wo16;
    cudaGetSymbolAddress((void**)&qhi, g_qhi);  cudaGetSymbolAddress((void**)&qlo, g_qlo);
    cudaGetSymbolAddress((void**)&k16, g_k16);  cudaGetSymbolAddress((void**)&v16, g_v16);
    cudaGetSymbolAddress((void**)&athi, g_athi); cudaGetSymbolAddress((void**)&atlo, g_atlo);
    cudaGetSymbolAddress((void**)&xqh, g_xqh);  cudaGetSymbolAddress((void**)&xql, g_xql);
    cudaGetSymbolAddress((void**)&xkh, g_xkh);  cudaGetSymbolAddress((void**)&xkl, g_xkl);
    cudaGetSymbolAddress((void**)&xvh, g_xvh);  cudaGetSymbolAddress((void**)&xvl, g_xvl);
    cudaGetSymbolAddress((void**)&wq16, g_wq16); cudaGetSymbolAddress((void**)&wk16, g_wk16);
    cudaGetSymbolAddress((void**)&wv16, g_wv16); cudaGetSymbolAddress((void**)&wo16, g_wo16);

    cudaFuncSetAttribute(gemm_qkv3, cudaFuncAttributeMaxDynamicSharedMemorySize, NT_SMEM);
    cudaFuncSetAttribute(gemm_wo, cudaFuncAttributeMaxDynamicSharedMemorySize, NT_SMEM);
    cudaFuncSetAttribute(fused_attn, cudaFuncAttributeMaxDynamicSharedMemorySize, FA_SMEM);

    const int M_rows = NBATCH * S_LEN;
    const int nact4 = (int)((size_t)M_rows * DMODEL / 4);
    const int nw4   = (int)((size_t)DMODEL * DMODEL / 4);
    dim3 blk(256);

    // 1) Split activations (hi/lo) and round weights to fp16
    {
        dim3 ga((nact4 + 255) / 256, 3);
        split_h3<<<ga, blk>>>(q, k, v, xqh, xql, xkh, xkl, xvh, xvl, nact4);
        dim3 gw((nw4 + 255) / 256, 4);
        conv_h4<<<gw, blk>>>(w_q, w_k, w_v, w_o, wq16, wk16, wv16, wo16, nw4);
    }

    // 2) QKV projections (one launch): Q split-out, K/V half-out
    {
        dim3 grid(DMODEL / 128, M_rows / 128, 3);
        gemm_qkv3<<<grid, blk, NT_SMEM>>>(
            xqh, xql, xkh, xkl, xvh, xvl,
            wq16, wk16, wv16,
            qhi, qlo, k16, v16);
    }

    // 3) Fused attention
    {
        dim3 grid(S_LEN / 128, NBATCH * NHEADS);
        fused_attn<<<grid, blk, FA_SMEM>>>(qhi, qlo, k16, v16, athi, atlo);
    }

    // 4) Output projection -> fp32 d_out
    {
        dim3 grid(DMODEL / 128, M_rows / 128);
        gemm_wo<<<grid, blk, NT_SMEM>>>(athi, atlo, wo16, out);
    }
}

// round 11
// speedup vs baseline: 2.3652x; 1.4566x over previous
#include <cuda_runtime.h>
#include <cuda_fp16.h>
#include <math.h>
#include <stdint.h>

#define S_LEN   2048
#define DMODEL  2048
#define NHEADS  16
#define DK      128
#define NBATCH  4

// ---------------- static device scratch (fp16) ------------------------------
__device__ __half g_x16[3][(size_t)NBATCH * S_LEN * DMODEL];   // q,k,v inputs
__device__ __half g_w16[4][(size_t)DMODEL * DMODEL];           // wq,wk,wv,wo
__device__ __half g_q16[(size_t)NBATCH * S_LEN * DMODEL];
__device__ __half g_k16[(size_t)NBATCH * S_LEN * DMODEL];
__device__ __half g_v16[(size_t)NBATCH * S_LEN * DMODEL];
__device__ __half g_athi[(size_t)NBATCH * S_LEN * DMODEL];
__device__ __half g_atlo[(size_t)NBATCH * S_LEN * DMODEL];

// ======================= PTX helpers =======================================
__device__ __forceinline__ uint32_t smem_u32(const void* p) {
    uint32_t a;
    asm("{ .reg .u64 t; cvta.to.shared.u64 t, %1; cvt.u32.u64 %0, t; }" : "=r"(a) : "l"(p));
    return a;
}
#define CP_ASYNC16(dst, src) asm volatile("cp.async.cg.shared.global [%0], [%1], 16;" :: "r"(dst), "l"(src))
#define CP_COMMIT()          asm volatile("cp.async.commit_group;" ::: "memory")
#define CP_WAIT0()           asm volatile("cp.async.wait_group 0;" ::: "memory")
#define CP_WAIT1()           asm volatile("cp.async.wait_group 1;" ::: "memory")

#define LDSM_X4(r0, r1, r2, r3, addr) \
    asm volatile("ldmatrix.sync.aligned.m8n8.x4.shared.b16 {%0,%1,%2,%3}, [%4];" \
        : "=r"(r0), "=r"(r1), "=r"(r2), "=r"(r3) : "r"(addr))
#define LDSM_X4_T(r0, r1, r2, r3, addr) \
    asm volatile("ldmatrix.sync.aligned.m8n8.x4.trans.shared.b16 {%0,%1,%2,%3}, [%4];" \
        : "=r"(r0), "=r"(r1), "=r"(r2), "=r"(r3) : "r"(addr))

#define MMA_F16(c, a, b0, b1) \
    asm volatile("mma.sync.aligned.m16n8k16.row.col.f32.f16.f16.f32 " \
        "{%0,%1,%2,%3},{%4,%5,%6,%7},{%8,%9},{%0,%1,%2,%3};" \
        : "+f"((c)[0]), "+f"((c)[1]), "+f"((c)[2]), "+f"((c)[3]) \
        : "r"((a)[0]), "r"((a)[1]), "r"((a)[2]), "r"((a)[3]), "r"(b0), "r"(b1))

__device__ __forceinline__ void split2h(float x, __half& h, __half& l) {
    h = __float2half_rn(x);
    l = __float2half_rn(x - __half2float(h));
}
__device__ __forceinline__ uint32_t packh(__half a, __half b) {
    __half2 t = __halves2half2(a, b);
    return *(uint32_t*)&t;
}

#define LDSB 80
#define ARR_BYTES (128 * LDSB)      // 10240

// ===========================================================================
// Pure fp16 1-pass NT GEMM: C[m,n] = sum_k A16[m,k] * B16[n,k] -> half C.
// Block 128x128, BK=32, 256 threads (8 warps 4m x 2n), double buffer.
// ===========================================================================
#define STG1 (2 * ARR_BYTES)        // 20480 (A, B)
#define SMEM1 (2 * STG1)            // 40960

__global__ __launch_bounds__(256, 2) void gemm_qkv3(
    const __half* __restrict__ xall,   // g_x16 base, 3 tensors contiguous
    const __half* __restrict__ wall,   // g_w16 base, 4 tensors contiguous
    __half* __restrict__ q16, __half* __restrict__ k16, __half* __restrict__ v16)
{
    extern __shared__ char smem[];
    const uint32_t sb = smem_u32(smem);
    const int tid  = threadIdx.x;
    const int lane = tid & 31, wid = tid >> 5;
    const int wm   = wid & 3, wn = wid >> 2;
    const int row0 = blockIdx.y * 128;
    const int col0 = blockIdx.x * 128;
    const int z    = blockIdx.z;

    const size_t NACT = (size_t)NBATCH * S_LEN * DMODEL;
    const size_t NW   = (size_t)DMODEL * DMODEL;
    const __half* A = xall + (size_t)z * NACT;
    const __half* B = wall + (size_t)z * NW;
    __half* C = (z == 0) ? q16 : ((z == 1) ? k16 : v16);

    const int nchunk = DMODEL >> 5;   // 64

    auto issue_stage = [&](int kt, int s) {
        const int k0 = kt << 5;
        const uint32_t sbase = sb + s * STG1;
#pragma unroll
        for (int i = 0; i < 2; i++) {
            const int c = tid + i * 256;
            const int r = c >> 2, q = c & 3;
            CP_ASYNC16(sbase + r * LDSB + q * 16,
                       A + (size_t)(row0 + r) * DMODEL + k0 + q * 8);
            CP_ASYNC16(sbase + ARR_BYTES + r * LDSB + q * 16,
                       B + (size_t)(col0 + r) * DMODEL + k0 + q * 8);
        }
        CP_COMMIT();
    };

    float acc[2][8][4];
#pragma unroll
    for (int mt = 0; mt < 2; mt++)
#pragma unroll
        for (int nt = 0; nt < 8; nt++)
#pragma unroll
            for (int r = 0; r < 4; r++) acc[mt][nt][r] = 0.0f;

    const int arow  = wm * 32 + (lane & 15);
    const int acolb = ((lane >> 4) << 3) * 2;
    const int brow  = wn * 64 + (lane & 7) + ((lane >> 4) & 1) * 8;
    const int bcolb = (((lane >> 3) & 1) << 3) * 2;

    auto compute_stage = [&](int s) {
        const uint32_t sbase = sb + s * STG1;
        const uint32_t sA = sbase;
        const uint32_t sB = sbase + ARR_BYTES;
#pragma unroll
        for (int h = 0; h < 2; h++) {
            const int kb = h * 32;
            uint32_t a0[4], a1[4];
            {
                uint32_t ad = sA + arow * LDSB + acolb + kb;
                LDSM_X4(a0[0], a0[1], a0[2], a0[3], ad);
                LDSM_X4(a1[0], a1[1], a1[2], a1[3], ad + 16 * LDSB);
            }
#pragma unroll
            for (int np = 0; np < 4; np++) {
                uint32_t bq[4];
                const uint32_t bo = (brow + np * 16) * LDSB + bcolb + kb;
                LDSM_X4(bq[0], bq[1], bq[2], bq[3], sB + bo);
#pragma unroll
                for (int u = 0; u < 2; u++) {
                    MMA_F16(acc[0][np * 2 + u], a0, bq[2 * u], bq[2 * u + 1]);
                    MMA_F16(acc[1][np * 2 + u], a1, bq[2 * u], bq[2 * u + 1]);
                }
            }
        }
    };

    issue_stage(0, 0);
    issue_stage(1, 1);
    for (int t = 0; t < nchunk; t++) {
        if (t + 2 < nchunk) { CP_WAIT1(); } else { CP_WAIT0(); }
        __syncthreads();
        compute_stage(t & 1);
        __syncthreads();
        if (t + 2 < nchunk) issue_stage(t + 2, t & 1);
    }

#pragma unroll
    for (int mt = 0; mt < 2; mt++) {
#pragma unroll
        for (int nt = 0; nt < 8; nt++) {
            const int r  = row0 + wm * 32 + mt * 16 + (lane >> 2);
            const int cc = col0 + wn * 64 + nt * 8 + (lane & 3) * 2;
            *(__half2*)(C + (size_t)r * DMODEL + cc) =
                __halves2half2(__float2half_rn(acc[mt][nt][0]), __float2half_rn(acc[mt][nt][1]));
            *(__half2*)(C + (size_t)(r + 8) * DMODEL + cc) =
                __halves2half2(__float2half_rn(acc[mt][nt][2]), __float2half_rn(acc[mt][nt][3]));
        }
    }
}

// ===========================================================================
// W_o projection: fp16 2-pass (A = attn hi/lo, B = wo16), fp32 out.
// ===========================================================================
#define STG2 (3 * ARR_BYTES)        // 30720 (Ahi, Alo, B)
#define SMEM2 (2 * STG2)            // 61440

__global__ __launch_bounds__(256, 2) void gemm_wo(
    const __half* __restrict__ Ahi, const __half* __restrict__ Alo,
    const __half* __restrict__ B16, float* __restrict__ Cf)
{
    extern __shared__ char smem[];
    const uint32_t sb = smem_u32(smem);
    const int tid  = threadIdx.x;
    const int lane = tid & 31, wid = tid >> 5;
    const int wm   = wid & 3, wn = wid >> 2;
    const int row0 = blockIdx.y * 128;
    const int col0 = blockIdx.x * 128;

    const __half* gsrc[3] = {Ahi, Alo, B16};
    const int nchunk = DMODEL >> 5;

    auto issue_stage = [&](int kt, int s) {
        const int k0 = kt << 5;
        const uint32_t sbase = sb + s * STG2;
#pragma unroll
        for (int a = 0; a < 3; a++) {
            const __half* g = gsrc[a];
            const int rbase = (a < 2) ? row0 : col0;
#pragma unroll
            for (int i = 0; i < 2; i++) {
                const int c = tid + i * 256;
                const int r = c >> 2, q = c & 3;
                CP_ASYNC16(sbase + a * ARR_BYTES + r * LDSB + q * 16,
                           g + (size_t)(rbase + r) * DMODEL + k0 + q * 8);
            }
        }
        CP_COMMIT();
    };

    float acc[2][8][4];
#pragma unroll
    for (int mt = 0; mt < 2; mt++)
#pragma unroll
        for (int nt = 0; nt < 8; nt++)
#pragma unroll
            for (int r = 0; r < 4; r++) acc[mt][nt][r] = 0.0f;

    const int arow  = wm * 32 + (lane & 15);
    const int acolb = ((lane >> 4) << 3) * 2;
    const int brow  = wn * 64 + (lane & 7) + ((lane >> 4) & 1) * 8;
    const int bcolb = (((lane >> 3) & 1) << 3) * 2;

    auto compute_stage = [&](int s) {
        const uint32_t sbase = sb + s * STG2;
        const uint32_t sAhi = sbase;
        const uint32_t sAlo = sbase + ARR_BYTES;
        const uint32_t sB   = sbase + 2 * ARR_BYTES;
#pragma unroll
        for (int h = 0; h < 2; h++) {
            const int kb = h * 32;
            uint32_t ah[2][4], al[2][4];
            {
                uint32_t a0 = sAhi + arow * LDSB + acolb + kb;
                LDSM_X4(ah[0][0], ah[0][1], ah[0][2], ah[0][3], a0);
                LDSM_X4(ah[1][0], ah[1][1], ah[1][2], ah[1][3], a0 + 16 * LDSB);
                uint32_t l0 = sAlo + arow * LDSB + acolb + kb;
                LDSM_X4(al[0][0], al[0][1], al[0][2], al[0][3], l0);
                LDSM_X4(al[1][0], al[1][1], al[1][2], al[1][3], l0 + 16 * LDSB);
            }
#pragma unroll
            for (int np = 0; np < 4; np++) {
                uint32_t bq[4];
                const uint32_t bo = (brow + np * 16) * LDSB + bcolb + kb;
                LDSM_X4(bq[0], bq[1], bq[2], bq[3], sB + bo);
#pragma unroll
                for (int mt = 0; mt < 2; mt++) {
#pragma unroll
                    for (int u = 0; u < 2; u++) {
                        float* c = acc[mt][np * 2 + u];
                        MMA_F16(c, ah[mt], bq[2 * u], bq[2 * u + 1]);
                        MMA_F16(c, al[mt], bq[2 * u], bq[2 * u + 1]);
                    }
                }
            }
        }
    };

    issue_stage(0, 0);
    issue_stage(1, 1);
    for (int t = 0; t < nchunk; t++) {
        if (t + 2 < nchunk) { CP_WAIT1(); } else { CP_WAIT0(); }
        __syncthreads();
        compute_stage(t & 1);
        __syncthreads();
        if (t + 2 < nchunk) issue_stage(t + 2, t & 1);
    }

#pragma unroll
    for (int mt = 0; mt < 2; mt++) {
#pragma unroll
        for (int nt = 0; nt < 8; nt++) {
            const int r  = row0 + wm * 32 + mt * 16 + (lane >> 2);
            const int cc = col0 + wn * 64 + nt * 8 + (lane & 3) * 2;
            float* p = Cf + (size_t)r * DMODEL + cc;
            *(float2*)p = make_float2(acc[mt][nt][0], acc[mt][nt][1]);
            *(float2*)(p + 8 * DMODEL) = make_float2(acc[mt][nt][2], acc[mt][nt][3]);
        }
    }
}

// ===========================================================================
// fp32 -> fp16 rounding, z-batched (3 activations, then 4 weights)
// ===========================================================================
__global__ __launch_bounds__(256) void conv_h(
    const float* __restrict__ x0, const float* __restrict__ x1,
    const float* __restrict__ x2, const float* __restrict__ x3,
    __half* __restrict__ y0, __half* __restrict__ y1,
    __half* __restrict__ y2, __half* __restrict__ y3, int n4)
{
    const int z = blockIdx.y;
    const float* x = (z == 0) ? x0 : ((z == 1) ? x1 : ((z == 2) ? x2 : x3));
    __half* y = (z == 0) ? y0 : ((z == 1) ? y1 : ((z == 2) ? y2 : y3));
    int i = blockIdx.x * 256 + threadIdx.x;
    if (i >= n4) return;
    float4 v = ((const float4*)x)[i];
    ((__half2*)y)[2 * i + 0] = __halves2half2(__float2half_rn(v.x), __float2half_rn(v.y));
    ((__half2*)y)[2 * i + 1] = __halves2half2(__float2half_rn(v.z), __float2half_rn(v.w));
}

// ===========================================================================
// Fused flash attention, pure fp16 1-pass:
//   S = Q K^T ; online softmax ; O += P V  (all operands single fp16)
// Output written as half hi/lo (exact split of fp32 accum) for the 2-pass W_o.
// ===========================================================================
#define FA_LDSB    272
#define FA_QTILE   (128 * FA_LDSB)               // 34816
#define FA_KVTILE  (64 * FA_LDSB)                // 17408
#define FA_KVSTG   (2 * FA_KVTILE)               // 34816 (K + V)
#define FA_SMEM    (FA_QTILE + 2 * FA_KVSTG)     // 104448

__global__ __launch_bounds__(256, 1) void fused_attn(
    const __half* __restrict__ Q16, const __half* __restrict__ K16,
    const __half* __restrict__ V16,
    __half* __restrict__ Ohi, __half* __restrict__ Olo)
{
    extern __shared__ char smem[];
    const uint32_t sb = smem_u32(smem);
    const int tid  = threadIdx.x;
    const int lane = tid & 31, wid = tid >> 5;
    const int qrow0 = blockIdx.x * 128;
    const int z  = blockIdx.y;
    const int bb = z >> 4, hh = z & 15;
    const size_t base = (size_t)bb * S_LEN * DMODEL + (size_t)hh * DK;

    const __half* qsrc = Q16 + base;
    const __half* kvsrc[2] = {K16 + base, V16 + base};

    const uint32_t sQ = sb;
    const uint32_t sKV = sb + FA_QTILE;

#pragma unroll
    for (int i = 0; i < 8; i++) {
        const int c = tid + i * 256;              // 0..2047
        const int r = c >> 4, q = c & 15;
        CP_ASYNC16(sQ + r * FA_LDSB + q * 16,
                   qsrc + (size_t)(qrow0 + r) * DMODEL + q * 8);
    }
    auto issue_stage = [&](int j, int s) {
        const int s0 = j << 6;
        const uint32_t sbase = sKV + s * FA_KVSTG;
#pragma unroll
        for (int i = 0; i < 8; i++) {
            const int c = tid + i * 256;          // 0..2047
            const int t = c >> 10, rem = c & 1023;
            const int r = rem >> 4, q = rem & 15;
            CP_ASYNC16(sbase + t * FA_KVTILE + r * FA_LDSB + q * 16,
                       kvsrc[t] + (size_t)(s0 + r) * DMODEL + q * 8);
        }
        CP_COMMIT();
    };
    issue_stage(0, 0);
    issue_stage(1, 1);

    float accO[16][4];
#pragma unroll
    for (int nt = 0; nt < 16; nt++)
#pragma unroll
        for (int r = 0; r < 4; r++) accO[nt][r] = 0.0f;
    float mrow[2] = {-1e30f, -1e30f};
    float lrow[2] = {0.0f, 0.0f};
    const float csc = 0.08838834764831845f;

    const int arow  = wid * 16 + (lane & 15);
    const int acolb = (lane >> 4) * 16;
    const int brow  = (lane & 7) + ((lane >> 4) & 1) * 8;
    const int bcolb = ((lane >> 3) & 1) * 16;
    const int btr   = (lane & 7) + ((lane >> 3) & 1) * 8;
    const int btc   = ((lane >> 4) & 1) * 8;

    const int NITER = S_LEN / 64;
    for (int j = 0; j < NITER; j++) {
        if (j + 2 < NITER) { CP_WAIT1(); } else { CP_WAIT0(); }
        __syncthreads();
        const uint32_t st = sKV + (j & 1) * FA_KVSTG;
        const uint32_t sK = st;
        const uint32_t sV = st + FA_KVTILE;

        float sacc[8][4];
#pragma unroll
        for (int nt = 0; nt < 8; nt++)
#pragma unroll
            for (int r = 0; r < 4; r++) sacc[nt][r] = 0.0f;

#pragma unroll
        for (int kst = 0; kst < 8; kst++) {
            const int kb = kst * 32;
            uint32_t qh[4];
            LDSM_X4(qh[0], qh[1], qh[2], qh[3], sQ + arow * FA_LDSB + acolb + kb);
#pragma unroll
            for (int np = 0; np < 4; np++) {
                const uint32_t bo = (uint32_t)(brow + np * 16) * FA_LDSB + bcolb + kb;
                uint32_t kq[4];
                LDSM_X4(kq[0], kq[1], kq[2], kq[3], sK + bo);
#pragma unroll
                for (int u = 0; u < 2; u++)
                    MMA_F16(sacc[np * 2 + u], qh, kq[2 * u], kq[2 * u + 1]);
            }
        }

        float mnew[2] = {mrow[0], mrow[1]};
#pragma unroll
        for (int nt = 0; nt < 8; nt++) {
            mnew[0] = fmaxf(mnew[0], fmaxf(sacc[nt][0], sacc[nt][1]));
            mnew[1] = fmaxf(mnew[1], fmaxf(sacc[nt][2], sacc[nt][3]));
        }
#pragma unroll
        for (int o = 1; o <= 2; o <<= 1) {
            mnew[0] = fmaxf(mnew[0], __shfl_xor_sync(0xffffffffu, mnew[0], o));
            mnew[1] = fmaxf(mnew[1], __shfl_xor_sync(0xffffffffu, mnew[1], o));
        }
        const float sc0 = __expf((mrow[0] - mnew[0]) * csc);
        const float sc1 = __expf((mrow[1] - mnew[1]) * csc);
        mrow[0] = mnew[0]; mrow[1] = mnew[1];
        lrow[0] *= sc0; lrow[1] *= sc1;
#pragma unroll
        for (int nt = 0; nt < 16; nt++) {
            accO[nt][0] *= sc0; accO[nt][1] *= sc0;
            accO[nt][2] *= sc1; accO[nt][3] *= sc1;
        }

        uint32_t ph[4][4];
        float ls0 = 0.0f, ls1 = 0.0f;
#pragma unroll
        for (int t2 = 0; t2 < 4; t2++) {
#pragma unroll
            for (int half = 0; half < 2; half++) {
                float* s = sacc[2 * t2 + half];
                float p0 = __expf((s[0] - mnew[0]) * csc);
                float p1 = __expf((s[1] - mnew[0]) * csc);
                float p2 = __expf((s[2] - mnew[1]) * csc);
                float p3 = __expf((s[3] - mnew[1]) * csc);
                ls0 += p0 + p1; ls1 += p2 + p3;
                ph[t2][2 * half + 0] = packh(__float2half_rn(p0), __float2half_rn(p1));
                ph[t2][2 * half + 1] = packh(__float2half_rn(p2), __float2half_rn(p3));
            }
        }
        lrow[0] += ls0; lrow[1] += ls1;

#pragma unroll
        for (int t2 = 0; t2 < 4; t2++) {
#pragma unroll
            for (int np = 0; np < 8; np++) {
                const uint32_t bo = (uint32_t)(t2 * 16 + btr) * FA_LDSB + (np * 16 + btc) * 2;
                uint32_t vq[4];
                LDSM_X4_T(vq[0], vq[1], vq[2], vq[3], sV + bo);
#pragma unroll
                for (int u = 0; u < 2; u++)
                    MMA_F16(accO[np * 2 + u], ph[t2], vq[2 * u], vq[2 * u + 1]);
            }
        }

        __syncthreads();
        if (j + 2 < NITER) issue_stage(j + 2, j & 1);
    }

#pragma unroll
    for (int o = 1; o <= 2; o <<= 1) {
        lrow[0] += __shfl_xor_sync(0xffffffffu, lrow[0], o);
        lrow[1] += __shfl_xor_sync(0xffffffffu, lrow[1], o);
    }
    const float inv0 = 1.0f / lrow[0];
    const float inv1 = 1.0f / lrow[1];
    const int r0 = qrow0 + wid * 16 + (lane >> 2);
#pragma unroll
    for (int nt = 0; nt < 16; nt++) {
        const int cc = nt * 8 + (lane & 3) * 2;
        __half h0, h1, l0, l1;
        split2h(accO[nt][0] * inv0, h0, l0);
        split2h(accO[nt][1] * inv0, h1, l1);
        *(__half2*)(Ohi + base + (size_t)r0 * DMODEL + cc) = __halves2half2(h0, h1);
        *(__half2*)(Olo + base + (size_t)r0 * DMODEL + cc) = __halves2half2(l0, l1);
        split2h(accO[nt][2] * inv1, h0, l0);
        split2h(accO[nt][3] * inv1, h1, l1);
        *(__half2*)(Ohi + base + (size_t)(r0 + 8) * DMODEL + cc) = __halves2half2(h0, h1);
        *(__half2*)(Olo + base + (size_t)(r0 + 8) * DMODEL + cc) = __halves2half2(l0, l1);
    }
}

// ---------------------------------------------------------------------------
extern "C" void kernel_launch(void* const* d_in, const int* in_sizes, int n_in,
                              void* d_out, int out_size)
{
    const float* q   = (const float*)d_in[0];
    const float* k   = (const float*)d_in[1];
    const float* v   = (const float*)d_in[2];
    const float* w_q = (const float*)d_in[3];
    const float* w_k = (const float*)d_in[4];
    const float* w_v = (const float*)d_in[5];
    const float* w_o = (const float*)d_in[6];
    float* out = (float*)d_out;

    __half *x16, *w16, *q16, *k16, *v16, *athi, *atlo;
    cudaGetSymbolAddress((void**)&x16, g_x16);
    cudaGetSymbolAddress((void**)&w16, g_w16);
    cudaGetSymbolAddress((void**)&q16, g_q16);
    cudaGetSymbolAddress((void**)&k16, g_k16);
    cudaGetSymbolAddress((void**)&v16, g_v16);
    cudaGetSymbolAddress((void**)&athi, g_athi);
    cudaGetSymbolAddress((void**)&atlo, g_atlo);

    cudaFuncSetAttribute(gemm_qkv3, cudaFuncAttributeMaxDynamicSharedMemorySize, SMEM1);
    cudaFuncSetAttribute(gemm_wo, cudaFuncAttributeMaxDynamicSharedMemorySize, SMEM2);
    cudaFuncSetAttribute(fused_attn, cudaFuncAttributeMaxDynamicSharedMemorySize, FA_SMEM);

    const int M_rows = NBATCH * S_LEN;
    const size_t NACT = (size_t)M_rows * DMODEL;
    const size_t NW   = (size_t)DMODEL * DMODEL;
    const int nact4 = (int)(NACT / 4);
    const int nw4   = (int)(NW / 4);
    dim3 blk(256);

    // 1) Round inputs and weights to fp16
    {
        dim3 ga((nact4 + 255) / 256, 3);
        conv_h<<<ga, blk>>>(q, k, v, nullptr,
                            x16, x16 + NACT, x16 + 2 * NACT, nullptr, nact4);
        dim3 gw((nw4 + 255) / 256, 4);
        conv_h<<<gw, blk>>>(w_q, w_k, w_v, w_o,
                            w16, w16 + NW, w16 + 2 * NW, w16 + 3 * NW, nw4);
    }

    // 2) QKV projections (pure fp16 1-pass, one launch)
    {
        dim3 grid(DMODEL / 128, M_rows / 128, 3);
        gemm_qkv3<<<grid, blk, SMEM1>>>(x16, w16, q16, k16, v16);
    }

    // 3) Fused attention (pure fp16 1-pass), attn emitted as hi/lo
    {
        dim3 grid(S_LEN / 128, NBATCH * NHEADS);
        fused_attn<<<grid, blk, FA_SMEM>>>(q16, k16, v16, athi, atlo);
    }

    // 4) Output projection (2-pass: attn hi/lo x wo16) -> fp32 d_out
    {
        dim3 grid(DMODEL / 128, M_rows / 128);
        gemm_wo<<<grid, blk, SMEM2>>>(athi, atlo, w16 + 3 * NW, out);
    }
}

// round 12
// speedup vs baseline: 2.6139x; 1.1051x over previous
#include <cuda_runtime.h>
#include <cuda_fp16.h>
#include <math.h>
#include <stdint.h>

#define S_LEN   2048
#define DMODEL  2048
#define NHEADS  16
#define DK      128
#define NBATCH  4

// ---------------- static device scratch (fp16) ------------------------------
__device__ __half g_x16[3][(size_t)NBATCH * S_LEN * DMODEL];   // q,k,v inputs
__device__ __half g_w16[4][(size_t)DMODEL * DMODEL];           // wq,wk,wv,wo
__device__ __half g_q16[(size_t)NBATCH * S_LEN * DMODEL];
__device__ __half g_k16[(size_t)NBATCH * S_LEN * DMODEL];
__device__ __half g_v16[(size_t)NBATCH * S_LEN * DMODEL];
__device__ __half g_at16[(size_t)NBATCH * S_LEN * DMODEL];

// ======================= PTX helpers =======================================
__device__ __forceinline__ uint32_t smem_u32(const void* p) {
    uint32_t a;
    asm("{ .reg .u64 t; cvta.to.shared.u64 t, %1; cvt.u32.u64 %0, t; }" : "=r"(a) : "l"(p));
    return a;
}
#define CP_ASYNC16(dst, src) asm volatile("cp.async.cg.shared.global [%0], [%1], 16;" :: "r"(dst), "l"(src))
#define CP_COMMIT()          asm volatile("cp.async.commit_group;" ::: "memory")
#define CP_WAIT0()           asm volatile("cp.async.wait_group 0;" ::: "memory")
#define CP_WAIT1()           asm volatile("cp.async.wait_group 1;" ::: "memory")

#define LDSM_X4(r0, r1, r2, r3, addr) \
    asm volatile("ldmatrix.sync.aligned.m8n8.x4.shared.b16 {%0,%1,%2,%3}, [%4];" \
        : "=r"(r0), "=r"(r1), "=r"(r2), "=r"(r3) : "r"(addr))
#define LDSM_X4_T(r0, r1, r2, r3, addr) \
    asm volatile("ldmatrix.sync.aligned.m8n8.x4.trans.shared.b16 {%0,%1,%2,%3}, [%4];" \
        : "=r"(r0), "=r"(r1), "=r"(r2), "=r"(r3) : "r"(addr))

#define MMA_F16(c, a, b0, b1) \
    asm volatile("mma.sync.aligned.m16n8k16.row.col.f32.f16.f16.f32 " \
        "{%0,%1,%2,%3},{%4,%5,%6,%7},{%8,%9},{%0,%1,%2,%3};" \
        : "+f"((c)[0]), "+f"((c)[1]), "+f"((c)[2]), "+f"((c)[3]) \
        : "r"((a)[0]), "r"((a)[1]), "r"((a)[2]), "r"((a)[3]), "r"(b0), "r"(b1))

__device__ __forceinline__ uint32_t packh(__half a, __half b) {
    __half2 t = __halves2half2(a, b);
    return *(uint32_t*)&t;
}

#define LDSB 80
#define ARR_BYTES (128 * LDSB)      // 10240

// ===========================================================================
// Pure fp16 1-pass NT GEMM body: C[m,n] = sum_k A16[m,k] * B16[n,k]
// Block 128x128, BK=32, 256 threads (8 warps 4m x 2n), double buffer.
// outf == nullptr -> write half C16; else write fp32 outf.
// ===========================================================================
#define STG1 (2 * ARR_BYTES)        // 20480 (A, B)
#define SMEM1 (2 * STG1)            // 40960

__device__ __forceinline__ void gemm1_body(
    const __half* __restrict__ A, const __half* __restrict__ B,
    __half* __restrict__ C16, float* __restrict__ Cf)
{
    extern __shared__ char smem[];
    const uint32_t sb = smem_u32(smem);
    const int tid  = threadIdx.x;
    const int lane = tid & 31, wid = tid >> 5;
    const int wm   = wid & 3, wn = wid >> 2;
    const int row0 = blockIdx.y * 128;
    const int col0 = blockIdx.x * 128;

    const int nchunk = DMODEL >> 5;   // 64

    auto issue_stage = [&](int kt, int s) {
        const int k0 = kt << 5;
        const uint32_t sbase = sb + s * STG1;
#pragma unroll
        for (int i = 0; i < 2; i++) {
            const int c = tid + i * 256;
            const int r = c >> 2, q = c & 3;
            CP_ASYNC16(sbase + r * LDSB + q * 16,
                       A + (size_t)(row0 + r) * DMODEL + k0 + q * 8);
            CP_ASYNC16(sbase + ARR_BYTES + r * LDSB + q * 16,
                       B + (size_t)(col0 + r) * DMODEL + k0 + q * 8);
        }
        CP_COMMIT();
    };

    float acc[2][8][4];
#pragma unroll
    for (int mt = 0; mt < 2; mt++)
#pragma unroll
        for (int nt = 0; nt < 8; nt++)
#pragma unroll
            for (int r = 0; r < 4; r++) acc[mt][nt][r] = 0.0f;

    const int arow  = wm * 32 + (lane & 15);
    const int acolb = ((lane >> 4) << 3) * 2;
    const int brow  = wn * 64 + (lane & 7) + ((lane >> 4) & 1) * 8;
    const int bcolb = (((lane >> 3) & 1) << 3) * 2;

    auto compute_stage = [&](int s) {
        const uint32_t sbase = sb + s * STG1;
        const uint32_t sA = sbase;
        const uint32_t sB = sbase + ARR_BYTES;
#pragma unroll
        for (int h = 0; h < 2; h++) {
            const int kb = h * 32;
            uint32_t a0[4], a1[4];
            {
                uint32_t ad = sA + arow * LDSB + acolb + kb;
                LDSM_X4(a0[0], a0[1], a0[2], a0[3], ad);
                LDSM_X4(a1[0], a1[1], a1[2], a1[3], ad + 16 * LDSB);
            }
#pragma unroll
            for (int np = 0; np < 4; np++) {
                uint32_t bq[4];
                const uint32_t bo = (brow + np * 16) * LDSB + bcolb + kb;
                LDSM_X4(bq[0], bq[1], bq[2], bq[3], sB + bo);
#pragma unroll
                for (int u = 0; u < 2; u++) {
                    MMA_F16(acc[0][np * 2 + u], a0, bq[2 * u], bq[2 * u + 1]);
                    MMA_F16(acc[1][np * 2 + u], a1, bq[2 * u], bq[2 * u + 1]);
                }
            }
        }
    };

    issue_stage(0, 0);
    issue_stage(1, 1);
    for (int t = 0; t < nchunk; t++) {
        if (t + 2 < nchunk) { CP_WAIT1(); } else { CP_WAIT0(); }
        __syncthreads();
        compute_stage(t & 1);
        __syncthreads();
        if (t + 2 < nchunk) issue_stage(t + 2, t & 1);
    }

#pragma unroll
    for (int mt = 0; mt < 2; mt++) {
#pragma unroll
        for (int nt = 0; nt < 8; nt++) {
            const int r  = row0 + wm * 32 + mt * 16 + (lane >> 2);
            const int cc = col0 + wn * 64 + nt * 8 + (lane & 3) * 2;
            if (Cf == nullptr) {
                *(__half2*)(C16 + (size_t)r * DMODEL + cc) =
                    __halves2half2(__float2half_rn(acc[mt][nt][0]), __float2half_rn(acc[mt][nt][1]));
                *(__half2*)(C16 + (size_t)(r + 8) * DMODEL + cc) =
                    __halves2half2(__float2half_rn(acc[mt][nt][2]), __float2half_rn(acc[mt][nt][3]));
            } else {
                float* p = Cf + (size_t)r * DMODEL + cc;
                *(float2*)p = make_float2(acc[mt][nt][0], acc[mt][nt][1]);
                *(float2*)(p + 8 * DMODEL) = make_float2(acc[mt][nt][2], acc[mt][nt][3]);
            }
        }
    }
}

// QKV projections: one launch, z selects (x, W, out)
__global__ __launch_bounds__(256, 2) void gemm_qkv3(
    const __half* __restrict__ xall, const __half* __restrict__ wall,
    __half* __restrict__ q16, __half* __restrict__ k16, __half* __restrict__ v16)
{
    const int z = blockIdx.z;
    const size_t NACT = (size_t)NBATCH * S_LEN * DMODEL;
    const size_t NW   = (size_t)DMODEL * DMODEL;
    __half* C = (z == 0) ? q16 : ((z == 1) ? k16 : v16);
    gemm1_body(xall + (size_t)z * NACT, wall + (size_t)z * NW, C, nullptr);
}

// Output projection: 1-pass, fp32 out
__global__ __launch_bounds__(256, 2) void gemm_wo(
    const __half* __restrict__ A16, const __half* __restrict__ B16,
    float* __restrict__ Cf)
{
    gemm1_body(A16, B16, nullptr, Cf);
}

// ===========================================================================
// fp32 -> fp16 rounding, z-batched over up to 4 tensors
// ===========================================================================
__global__ __launch_bounds__(256) void conv_h(
    const float* __restrict__ x0, const float* __restrict__ x1,
    const float* __restrict__ x2, const float* __restrict__ x3,
    __half* __restrict__ y0, __half* __restrict__ y1,
    __half* __restrict__ y2, __half* __restrict__ y3, int n4)
{
    const int z = blockIdx.y;
    const float* x = (z == 0) ? x0 : ((z == 1) ? x1 : ((z == 2) ? x2 : x3));
    __half* y = (z == 0) ? y0 : ((z == 1) ? y1 : ((z == 2) ? y2 : y3));
    int i = blockIdx.x * 256 + threadIdx.x;
    if (i >= n4) return;
    float4 v = ((const float4*)x)[i];
    ((__half2*)y)[2 * i + 0] = __halves2half2(__float2half_rn(v.x), __float2half_rn(v.y));
    ((__half2*)y)[2 * i + 1] = __halves2half2(__float2half_rn(v.z), __float2half_rn(v.w));
}

// ===========================================================================
// Fused flash attention, pure fp16 1-pass; attn out single fp16.
// ===========================================================================
#define FA_LDSB    272
#define FA_QTILE   (128 * FA_LDSB)               // 34816
#define FA_KVTILE  (64 * FA_LDSB)                // 17408
#define FA_KVSTG   (2 * FA_KVTILE)               // 34816 (K + V)
#define FA_SMEM    (FA_QTILE + 2 * FA_KVSTG)     // 104448

__global__ __launch_bounds__(256, 1) void fused_attn(
    const __half* __restrict__ Q16, const __half* __restrict__ K16,
    const __half* __restrict__ V16, __half* __restrict__ O16)
{
    extern __shared__ char smem[];
    const uint32_t sb = smem_u32(smem);
    const int tid  = threadIdx.x;
    const int lane = tid & 31, wid = tid >> 5;
    const int qrow0 = blockIdx.x * 128;
    const int z  = blockIdx.y;
    const int bb = z >> 4, hh = z & 15;
    const size_t base = (size_t)bb * S_LEN * DMODEL + (size_t)hh * DK;

    const __half* qsrc = Q16 + base;
    const __half* kvsrc[2] = {K16 + base, V16 + base};

    const uint32_t sQ = sb;
    const uint32_t sKV = sb + FA_QTILE;

#pragma unroll
    for (int i = 0; i < 8; i++) {
        const int c = tid + i * 256;              // 0..2047
        const int r = c >> 4, q = c & 15;
        CP_ASYNC16(sQ + r * FA_LDSB + q * 16,
                   qsrc + (size_t)(qrow0 + r) * DMODEL + q * 8);
    }
    auto issue_stage = [&](int j, int s) {
        const int s0 = j << 6;
        const uint32_t sbase = sKV + s * FA_KVSTG;
#pragma unroll
        for (int i = 0; i < 8; i++) {
            const int c = tid + i * 256;          // 0..2047
            const int t = c >> 10, rem = c & 1023;
            const int r = rem >> 4, q = rem & 15;
            CP_ASYNC16(sbase + t * FA_KVTILE + r * FA_LDSB + q * 16,
                       kvsrc[t] + (size_t)(s0 + r) * DMODEL + q * 8);
        }
        CP_COMMIT();
    };
    issue_stage(0, 0);
    issue_stage(1, 1);

    float accO[16][4];
#pragma unroll
    for (int nt = 0; nt < 16; nt++)
#pragma unroll
        for (int r = 0; r < 4; r++) accO[nt][r] = 0.0f;
    float mrow[2] = {-1e30f, -1e30f};
    float lrow[2] = {0.0f, 0.0f};
    const float csc = 0.08838834764831845f;

    const int arow  = wid * 16 + (lane & 15);
    const int acolb = (lane >> 4) * 16;
    const int brow  = (lane & 7) + ((lane >> 4) & 1) * 8;
    const int bcolb = ((lane >> 3) & 1) * 16;
    const int btr   = (lane & 7) + ((lane >> 3) & 1) * 8;
    const int btc   = ((lane >> 4) & 1) * 8;

    const int NITER = S_LEN / 64;
    for (int j = 0; j < NITER; j++) {
        if (j + 2 < NITER) { CP_WAIT1(); } else { CP_WAIT0(); }
        __syncthreads();
        const uint32_t st = sKV + (j & 1) * FA_KVSTG;
        const uint32_t sK = st;
        const uint32_t sV = st + FA_KVTILE;

        float sacc[8][4];
#pragma unroll
        for (int nt = 0; nt < 8; nt++)
#pragma unroll
            for (int r = 0; r < 4; r++) sacc[nt][r] = 0.0f;

#pragma unroll
        for (int kst = 0; kst < 8; kst++) {
            const int kb = kst * 32;
            uint32_t qh[4];
            LDSM_X4(qh[0], qh[1], qh[2], qh[3], sQ + arow * FA_LDSB + acolb + kb);
#pragma unroll
            for (int np = 0; np < 4; np++) {
                const uint32_t bo = (uint32_t)(brow + np * 16) * FA_LDSB + bcolb + kb;
                uint32_t kq[4];
                LDSM_X4(kq[0], kq[1], kq[2], kq[3], sK + bo);
#pragma unroll
                for (int u = 0; u < 2; u++)
                    MMA_F16(sacc[np * 2 + u], qh, kq[2 * u], kq[2 * u + 1]);
            }
        }

        float mnew[2] = {mrow[0], mrow[1]};
#pragma unroll
        for (int nt = 0; nt < 8; nt++) {
            mnew[0] = fmaxf(mnew[0], fmaxf(sacc[nt][0], sacc[nt][1]));
            mnew[1] = fmaxf(mnew[1], fmaxf(sacc[nt][2], sacc[nt][3]));
        }
#pragma unroll
        for (int o = 1; o <= 2; o <<= 1) {
            mnew[0] = fmaxf(mnew[0], __shfl_xor_sync(0xffffffffu, mnew[0], o));
            mnew[1] = fmaxf(mnew[1], __shfl_xor_sync(0xffffffffu, mnew[1], o));
        }
        const float sc0 = __expf((mrow[0] - mnew[0]) * csc);
        const float sc1 = __expf((mrow[1] - mnew[1]) * csc);
        mrow[0] = mnew[0]; mrow[1] = mnew[1];
        lrow[0] *= sc0; lrow[1] *= sc1;
#pragma unroll
        for (int nt = 0; nt < 16; nt++) {
            accO[nt][0] *= sc0; accO[nt][1] *= sc0;
            accO[nt][2] *= sc1; accO[nt][3] *= sc1;
        }

        uint32_t ph[4][4];
        float ls0 = 0.0f, ls1 = 0.0f;
#pragma unroll
        for (int t2 = 0; t2 < 4; t2++) {
#pragma unroll
            for (int half = 0; half < 2; half++) {
                float* s = sacc[2 * t2 + half];
                float p0 = __expf((s[0] - mnew[0]) * csc);
                float p1 = __expf((s[1] - mnew[0]) * csc);
                float p2 = __expf((s[2] - mnew[1]) * csc);
                float p3 = __expf((s[3] - mnew[1]) * csc);
                ls0 += p0 + p1; ls1 += p2 + p3;
                ph[t2][2 * half + 0] = packh(__float2half_rn(p0), __float2half_rn(p1));
                ph[t2][2 * half + 1] = packh(__float2half_rn(p2), __float2half_rn(p3));
            }
        }
        lrow[0] += ls0; lrow[1] += ls1;

#pragma unroll
        for (int t2 = 0; t2 < 4; t2++) {
#pragma unroll
            for (int np = 0; np < 8; np++) {
                const uint32_t bo = (uint32_t)(t2 * 16 + btr) * FA_LDSB + (np * 16 + btc) * 2;
                uint32_t vq[4];
                LDSM_X4_T(vq[0], vq[1], vq[2], vq[3], sV + bo);
#pragma unroll
                for (int u = 0; u < 2; u++)
                    MMA_F16(accO[np * 2 + u], ph[t2], vq[2 * u], vq[2 * u + 1]);
            }
        }

        __syncthreads();
        if (j + 2 < NITER) issue_stage(j + 2, j & 1);
    }

#pragma unroll
    for (int o = 1; o <= 2; o <<= 1) {
        lrow[0] += __shfl_xor_sync(0xffffffffu, lrow[0], o);
        lrow[1] += __shfl_xor_sync(0xffffffffu, lrow[1], o);
    }
    const float inv0 = 1.0f / lrow[0];
    const float inv1 = 1.0f / lrow[1];
    const int r0 = qrow0 + wid * 16 + (lane >> 2);
#pragma unroll
    for (int nt = 0; nt < 16; nt++) {
        const int cc = nt * 8 + (lane & 3) * 2;
        *(__half2*)(O16 + base + (size_t)r0 * DMODEL + cc) =
            __halves2half2(__float2half_rn(accO[nt][0] * inv0),
                           __float2half_rn(accO[nt][1] * inv0));
        *(__half2*)(O16 + base + (size_t)(r0 + 8) * DMODEL + cc) =
            __halves2half2(__float2half_rn(accO[nt][2] * inv1),
                           __float2half_rn(accO[nt][3] * inv1));
    }
}

// ---------------------------------------------------------------------------
extern "C" void kernel_launch(void* const* d_in, const int* in_sizes, int n_in,
                              void* d_out, int out_size)
{
    const float* q   = (const float*)d_in[0];
    const float* k   = (const float*)d_in[1];
    const float* v   = (const float*)d_in[2];
    const float* w_q = (const float*)d_in[3];
    const float* w_k = (const float*)d_in[4];
    const float* w_v = (const float*)d_in[5];
    const float* w_o = (const float*)d_in[6];
    float* out = (float*)d_out;

    __half *x16, *w16, *q16, *k16, *v16, *at16;
    cudaGetSymbolAddress((void**)&x16, g_x16);
    cudaGetSymbolAddress((void**)&w16, g_w16);
    cudaGetSymbolAddress((void**)&q16, g_q16);
    cudaGetSymbolAddress((void**)&k16, g_k16);
    cudaGetSymbolAddress((void**)&v16, g_v16);
    cudaGetSymbolAddress((void**)&at16, g_at16);

    cudaFuncSetAttribute(gemm_qkv3, cudaFuncAttributeMaxDynamicSharedMemorySize, SMEM1);
    cudaFuncSetAttribute(gemm_wo, cudaFuncAttributeMaxDynamicSharedMemorySize, SMEM1);
    cudaFuncSetAttribute(fused_attn, cudaFuncAttributeMaxDynamicSharedMemorySize, FA_SMEM);

    const int M_rows = NBATCH * S_LEN;
    const size_t NACT = (size_t)M_rows * DMODEL;
    const size_t NW   = (size_t)DMODEL * DMODEL;
    const int nact4 = (int)(NACT / 4);
    const int nw4   = (int)(NW / 4);
    dim3 blk(256);

    // 1) Round inputs and weights to fp16
    {
        dim3 ga((nact4 + 255) / 256, 3);
        conv_h<<<ga, blk>>>(q, k, v, nullptr,
                            x16, x16 + NACT, x16 + 2 * NACT, nullptr, nact4);
        dim3 gw((nw4 + 255) / 256, 4);
        conv_h<<<gw, blk>>>(w_q, w_k, w_v, w_o,
                            w16, w16 + NW, w16 + 2 * NW, w16 + 3 * NW, nw4);
    }

    // 2) QKV projections (pure fp16 1-pass, one launch)
    {
        dim3 grid(DMODEL / 128, M_rows / 128, 3);
        gemm_qkv3<<<grid, blk, SMEM1>>>(x16, w16, q16, k16, v16);
    }

    // 3) Fused attention (pure fp16), attn single fp16
    {
        dim3 grid(S_LEN / 128, NBATCH * NHEADS);
        fused_attn<<<grid, blk, FA_SMEM>>>(q16, k16, v16, at16);
    }

    // 4) Output projection (pure fp16 1-pass) -> fp32 d_out
    {
        dim3 grid(DMODEL / 128, M_rows / 128);
        gemm_wo<<<grid, blk, SMEM1>>>(at16, w16 + 3 * NW, out);
    }
}

// round 13
// speedup vs baseline: 2.6400x; 1.0100x over previous
#include <cuda_runtime.h>
#include <cuda_fp16.h>
#include <math.h>
#include <stdint.h>

#define S_LEN   2048
#define DMODEL  2048
#define NHEADS  16
#define DK      128
#define NBATCH  4

// ---------------- static device scratch (fp16) ------------------------------
__device__ __half g_x16[3][(size_t)NBATCH * S_LEN * DMODEL];   // q,k,v inputs
__device__ __half g_w16[4][(size_t)DMODEL * DMODEL];           // wq,wk,wv,wo
__device__ __half g_q16[(size_t)NBATCH * S_LEN * DMODEL];
__device__ __half g_k16[(size_t)NBATCH * S_LEN * DMODEL];
__device__ __half g_v16[(size_t)NBATCH * S_LEN * DMODEL];
__device__ __half g_at16[(size_t)NBATCH * S_LEN * DMODEL];

// ======================= PTX helpers =======================================
__device__ __forceinline__ uint32_t smem_u32(const void* p) {
    uint32_t a;
    asm("{ .reg .u64 t; cvta.to.shared.u64 t, %1; cvt.u32.u64 %0, t; }" : "=r"(a) : "l"(p));
    return a;
}
#define CP_ASYNC16(dst, src) asm volatile("cp.async.cg.shared.global [%0], [%1], 16;" :: "r"(dst), "l"(src))
#define CP_COMMIT()          asm volatile("cp.async.commit_group;" ::: "memory")
#define CP_WAIT0()           asm volatile("cp.async.wait_group 0;" ::: "memory")
#define CP_WAIT1()           asm volatile("cp.async.wait_group 1;" ::: "memory")

#define LDSM_X4(r0, r1, r2, r3, addr) \
    asm volatile("ldmatrix.sync.aligned.m8n8.x4.shared.b16 {%0,%1,%2,%3}, [%4];" \
        : "=r"(r0), "=r"(r1), "=r"(r2), "=r"(r3) : "r"(addr))
#define LDSM_X4_T(r0, r1, r2, r3, addr) \
    asm volatile("ldmatrix.sync.aligned.m8n8.x4.trans.shared.b16 {%0,%1,%2,%3}, [%4];" \
        : "=r"(r0), "=r"(r1), "=r"(r2), "=r"(r3) : "r"(addr))

#define MMA_F16(c, a, b0, b1) \
    asm volatile("mma.sync.aligned.m16n8k16.row.col.f32.f16.f16.f32 " \
        "{%0,%1,%2,%3},{%4,%5,%6,%7},{%8,%9},{%0,%1,%2,%3};" \
        : "+f"((c)[0]), "+f"((c)[1]), "+f"((c)[2]), "+f"((c)[3]) \
        : "r"((a)[0]), "r"((a)[1]), "r"((a)[2]), "r"((a)[3]), "r"(b0), "r"(b1))

__device__ __forceinline__ uint32_t packh(__half a, __half b) {
    __half2 t = __halves2half2(a, b);
    return *(uint32_t*)&t;
}

#define LDSB 80
#define ARR_BYTES (128 * LDSB)      // 10240

// ===========================================================================
// Pure fp16 1-pass NT GEMM body (unchanged from Round 12)
// ===========================================================================
#define STG1 (2 * ARR_BYTES)        // 20480 (A, B)
#define SMEM1 (2 * STG1)            // 40960

__device__ __forceinline__ void gemm1_body(
    const __half* __restrict__ A, const __half* __restrict__ B,
    __half* __restrict__ C16, float* __restrict__ Cf)
{
    extern __shared__ char smem[];
    const uint32_t sb = smem_u32(smem);
    const int tid  = threadIdx.x;
    const int lane = tid & 31, wid = tid >> 5;
    const int wm   = wid & 3, wn = wid >> 2;
    const int row0 = blockIdx.y * 128;
    const int col0 = blockIdx.x * 128;

    const int nchunk = DMODEL >> 5;   // 64

    auto issue_stage = [&](int kt, int s) {
        const int k0 = kt << 5;
        const uint32_t sbase = sb + s * STG1;
#pragma unroll
        for (int i = 0; i < 2; i++) {
            const int c = tid + i * 256;
            const int r = c >> 2, q = c & 3;
            CP_ASYNC16(sbase + r * LDSB + q * 16,
                       A + (size_t)(row0 + r) * DMODEL + k0 + q * 8);
            CP_ASYNC16(sbase + ARR_BYTES + r * LDSB + q * 16,
                       B + (size_t)(col0 + r) * DMODEL + k0 + q * 8);
        }
        CP_COMMIT();
    };

    float acc[2][8][4];
#pragma unroll
    for (int mt = 0; mt < 2; mt++)
#pragma unroll
        for (int nt = 0; nt < 8; nt++)
#pragma unroll
            for (int r = 0; r < 4; r++) acc[mt][nt][r] = 0.0f;

    const int arow  = wm * 32 + (lane & 15);
    const int acolb = ((lane >> 4) << 3) * 2;
    const int brow  = wn * 64 + (lane & 7) + ((lane >> 4) & 1) * 8;
    const int bcolb = (((lane >> 3) & 1) << 3) * 2;

    auto compute_stage = [&](int s) {
        const uint32_t sbase = sb + s * STG1;
        const uint32_t sA = sbase;
        const uint32_t sB = sbase + ARR_BYTES;
#pragma unroll
        for (int h = 0; h < 2; h++) {
            const int kb = h * 32;
            uint32_t a0[4], a1[4];
            {
                uint32_t ad = sA + arow * LDSB + acolb + kb;
                LDSM_X4(a0[0], a0[1], a0[2], a0[3], ad);
                LDSM_X4(a1[0], a1[1], a1[2], a1[3], ad + 16 * LDSB);
            }
#pragma unroll
            for (int np = 0; np < 4; np++) {
                uint32_t bq[4];
                const uint32_t bo = (brow + np * 16) * LDSB + bcolb + kb;
                LDSM_X4(bq[0], bq[1], bq[2], bq[3], sB + bo);
#pragma unroll
                for (int u = 0; u < 2; u++) {
                    MMA_F16(acc[0][np * 2 + u], a0, bq[2 * u], bq[2 * u + 1]);
                    MMA_F16(acc[1][np * 2 + u], a1, bq[2 * u], bq[2 * u + 1]);
                }
            }
        }
    };

    issue_stage(0, 0);
    issue_stage(1, 1);
    for (int t = 0; t < nchunk; t++) {
        if (t + 2 < nchunk) { CP_WAIT1(); } else { CP_WAIT0(); }
        __syncthreads();
        compute_stage(t & 1);
        __syncthreads();
        if (t + 2 < nchunk) issue_stage(t + 2, t & 1);
    }

#pragma unroll
    for (int mt = 0; mt < 2; mt++) {
#pragma unroll
        for (int nt = 0; nt < 8; nt++) {
            const int r  = row0 + wm * 32 + mt * 16 + (lane >> 2);
            const int cc = col0 + wn * 64 + nt * 8 + (lane & 3) * 2;
            if (Cf == nullptr) {
                *(__half2*)(C16 + (size_t)r * DMODEL + cc) =
                    __halves2half2(__float2half_rn(acc[mt][nt][0]), __float2half_rn(acc[mt][nt][1]));
                *(__half2*)(C16 + (size_t)(r + 8) * DMODEL + cc) =
                    __halves2half2(__float2half_rn(acc[mt][nt][2]), __float2half_rn(acc[mt][nt][3]));
            } else {
                float* p = Cf + (size_t)r * DMODEL + cc;
                *(float2*)p = make_float2(acc[mt][nt][0], acc[mt][nt][1]);
                *(float2*)(p + 8 * DMODEL) = make_float2(acc[mt][nt][2], acc[mt][nt][3]);
            }
        }
    }
}

__global__ __launch_bounds__(256, 2) void gemm_qkv3(
    const __half* __restrict__ xall, const __half* __restrict__ wall,
    __half* __restrict__ q16, __half* __restrict__ k16, __half* __restrict__ v16)
{
    const int z = blockIdx.z;
    const size_t NACT = (size_t)NBATCH * S_LEN * DMODEL;
    const size_t NW   = (size_t)DMODEL * DMODEL;
    __half* C = (z == 0) ? q16 : ((z == 1) ? k16 : v16);
    gemm1_body(xall + (size_t)z * NACT, wall + (size_t)z * NW, C, nullptr);
}

__global__ __launch_bounds__(256, 2) void gemm_wo(
    const __half* __restrict__ A16, const __half* __restrict__ B16,
    float* __restrict__ Cf)
{
    gemm1_body(A16, B16, nullptr, Cf);
}

// ===========================================================================
// fp32 -> fp16 rounding, z-batched over up to 4 tensors
// ===========================================================================
__global__ __launch_bounds__(256) void conv_h(
    const float* __restrict__ x0, const float* __restrict__ x1,
    const float* __restrict__ x2, const float* __restrict__ x3,
    __half* __restrict__ y0, __half* __restrict__ y1,
    __half* __restrict__ y2, __half* __restrict__ y3, int n4)
{
    const int z = blockIdx.y;
    const float* x = (z == 0) ? x0 : ((z == 1) ? x1 : ((z == 2) ? x2 : x3));
    __half* y = (z == 0) ? y0 : ((z == 1) ? y1 : ((z == 2) ? y2 : y3));
    int i = blockIdx.x * 256 + threadIdx.x;
    if (i >= n4) return;
    float4 v = ((const float4*)x)[i];
    ((__half2*)y)[2 * i + 0] = __halves2half2(__float2half_rn(v.x), __float2half_rn(v.y));
    ((__half2*)y)[2 * i + 1] = __halves2half2(__float2half_rn(v.z), __float2half_rn(v.w));
}

// ===========================================================================
// Fused flash attention, pure fp16:
// 128-thread CTA, 64 Q rows (4 warps x 16 rows), 2 CTAs/SM co-resident.
// K/V blocks of 64 s-rows, 2-stage cp.async pipeline.
// ===========================================================================
#define FA_LDSB    272
#define FA_QROWS   64
#define FA_QTILE   (FA_QROWS * FA_LDSB)          // 17408
#define FA_KVTILE  (64 * FA_LDSB)                // 17408
#define FA_KVSTG   (2 * FA_KVTILE)               // 34816 (K + V)
#define FA_SMEM    (FA_QTILE + 2 * FA_KVSTG)     // 87040

__global__ __launch_bounds__(128, 2) void fused_attn(
    const __half* __restrict__ Q16, const __half* __restrict__ K16,
    const __half* __restrict__ V16, __half* __restrict__ O16)
{
    extern __shared__ char smem[];
    const uint32_t sb = smem_u32(smem);
    const int tid  = threadIdx.x;
    const int lane = tid & 31, wid = tid >> 5;       // 4 warps x 16 rows
    const int qrow0 = blockIdx.x * FA_QROWS;
    const int z  = blockIdx.y;
    const int bb = z >> 4, hh = z & 15;
    const size_t base = (size_t)bb * S_LEN * DMODEL + (size_t)hh * DK;

    const __half* qsrc = Q16 + base;
    const __half* kvsrc[2] = {K16 + base, V16 + base};

    const uint32_t sQ = sb;
    const uint32_t sKV = sb + FA_QTILE;

    // Q prologue: 64 rows x 16 chunks = 1024 chunks / 128 threads
#pragma unroll
    for (int i = 0; i < 8; i++) {
        const int c = tid + i * 128;
        const int r = c >> 4, q = c & 15;
        CP_ASYNC16(sQ + r * FA_LDSB + q * 16,
                   qsrc + (size_t)(qrow0 + r) * DMODEL + q * 8);
    }
    auto issue_stage = [&](int j, int s) {
        const int s0 = j << 6;
        const uint32_t sbase = sKV + s * FA_KVSTG;
#pragma unroll
        for (int i = 0; i < 16; i++) {
            const int c = tid + i * 128;             // 0..2047
            const int t = c >> 10, rem = c & 1023;
            const int r = rem >> 4, q = rem & 15;
            CP_ASYNC16(sbase + t * FA_KVTILE + r * FA_LDSB + q * 16,
                       kvsrc[t] + (size_t)(s0 + r) * DMODEL + q * 8);
        }
        CP_COMMIT();
    };
    issue_stage(0, 0);
    issue_stage(1, 1);

    float accO[16][4];
#pragma unroll
    for (int nt = 0; nt < 16; nt++)
#pragma unroll
        for (int r = 0; r < 4; r++) accO[nt][r] = 0.0f;
    float mrow[2] = {-1e30f, -1e30f};
    float lrow[2] = {0.0f, 0.0f};
    const float csc = 0.08838834764831845f;

    const int arow  = wid * 16 + (lane & 15);
    const int acolb = (lane >> 4) * 16;
    const int brow  = (lane & 7) + ((lane >> 4) & 1) * 8;
    const int bcolb = ((lane >> 3) & 1) * 16;
    const int btr   = (lane & 7) + ((lane >> 3) & 1) * 8;
    const int btc   = ((lane >> 4) & 1) * 8;

    const int NITER = S_LEN / 64;                    // 32
    for (int j = 0; j < NITER; j++) {
        if (j + 2 < NITER) { CP_WAIT1(); } else { CP_WAIT0(); }
        __syncthreads();
        const uint32_t st = sKV + (j & 1) * FA_KVSTG;
        const uint32_t sK = st;
        const uint32_t sV = st + FA_KVTILE;

        // ---- S = Q K^T -----------------------------------------------------
        float sacc[8][4];
#pragma unroll
        for (int nt = 0; nt < 8; nt++)
#pragma unroll
            for (int r = 0; r < 4; r++) sacc[nt][r] = 0.0f;

#pragma unroll
        for (int kst = 0; kst < 8; kst++) {
            const int kb = kst * 32;
            uint32_t qh[4];
            LDSM_X4(qh[0], qh[1], qh[2], qh[3], sQ + arow * FA_LDSB + acolb + kb);
#pragma unroll
            for (int np = 0; np < 4; np++) {
                const uint32_t bo = (uint32_t)(brow + np * 16) * FA_LDSB + bcolb + kb;
                uint32_t kq[4];
                LDSM_X4(kq[0], kq[1], kq[2], kq[3], sK + bo);
#pragma unroll
                for (int u = 0; u < 2; u++)
                    MMA_F16(sacc[np * 2 + u], qh, kq[2 * u], kq[2 * u + 1]);
            }
        }

        // ---- online softmax (row stats) ------------------------------------
        float mnew[2] = {mrow[0], mrow[1]};
#pragma unroll
        for (int nt = 0; nt < 8; nt++) {
            mnew[0] = fmaxf(mnew[0], fmaxf(sacc[nt][0], sacc[nt][1]));
            mnew[1] = fmaxf(mnew[1], fmaxf(sacc[nt][2], sacc[nt][3]));
        }
#pragma unroll
        for (int o = 1; o <= 2; o <<= 1) {
            mnew[0] = fmaxf(mnew[0], __shfl_xor_sync(0xffffffffu, mnew[0], o));
            mnew[1] = fmaxf(mnew[1], __shfl_xor_sync(0xffffffffu, mnew[1], o));
        }
        const float sc0 = __expf((mrow[0] - mnew[0]) * csc);
        const float sc1 = __expf((mrow[1] - mnew[1]) * csc);
        mrow[0] = mnew[0]; mrow[1] = mnew[1];
        lrow[0] *= sc0; lrow[1] *= sc1;
#pragma unroll
        for (int nt = 0; nt < 16; nt++) {
            accO[nt][0] *= sc0; accO[nt][1] *= sc0;
            accO[nt][2] *= sc1; accO[nt][3] *= sc1;
        }

        // ---- P exp/pack interleaved with PV MMAs ---------------------------
        float ls0 = 0.0f, ls1 = 0.0f;
#pragma unroll
        for (int t2 = 0; t2 < 4; t2++) {
            uint32_t ph[4];
#pragma unroll
            for (int half = 0; half < 2; half++) {
                float* s = sacc[2 * t2 + half];
                float p0 = __expf((s[0] - mnew[0]) * csc);
                float p1 = __expf((s[1] - mnew[0]) * csc);
                float p2 = __expf((s[2] - mnew[1]) * csc);
                float p3 = __expf((s[3] - mnew[1]) * csc);
                ls0 += p0 + p1; ls1 += p2 + p3;
                ph[2 * half + 0] = packh(__float2half_rn(p0), __float2half_rn(p1));
                ph[2 * half + 1] = packh(__float2half_rn(p2), __float2half_rn(p3));
            }
#pragma unroll
            for (int np = 0; np < 8; np++) {
                const uint32_t bo = (uint32_t)(t2 * 16 + btr) * FA_LDSB + (np * 16 + btc) * 2;
                uint32_t vq[4];
                LDSM_X4_T(vq[0], vq[1], vq[2], vq[3], sV + bo);
#pragma unroll
                for (int u = 0; u < 2; u++)
                    MMA_F16(accO[np * 2 + u], ph, vq[2 * u], vq[2 * u + 1]);
            }
        }
        lrow[0] += ls0; lrow[1] += ls1;

        __syncthreads();
        if (j + 2 < NITER) issue_stage(j + 2, j & 1);
    }

    // ---- epilogue ----------------------------------------------------------
#pragma unroll
    for (int o = 1; o <= 2; o <<= 1) {
        lrow[0] += __shfl_xor_sync(0xffffffffu, lrow[0], o);
        lrow[1] += __shfl_xor_sync(0xffffffffu, lrow[1], o);
    }
    const float inv0 = 1.0f / lrow[0];
    const float inv1 = 1.0f / lrow[1];
    const int r0 = qrow0 + wid * 16 + (lane >> 2);
#pragma unroll
    for (int nt = 0; nt < 16; nt++) {
        const int cc = nt * 8 + (lane & 3) * 2;
        *(__half2*)(O16 + base + (size_t)r0 * DMODEL + cc) =
            __halves2half2(__float2half_rn(accO[nt][0] * inv0),
                           __float2half_rn(accO[nt][1] * inv0));
        *(__half2*)(O16 + base + (size_t)(r0 + 8) * DMODEL + cc) =
            __halves2half2(__float2half_rn(accO[nt][2] * inv1),
                           __float2half_rn(accO[nt][3] * inv1));
    }
}

// ---------------------------------------------------------------------------
extern "C" void kernel_launch(void* const* d_in, const int* in_sizes, int n_in,
                              void* d_out, int out_size)
{
    const float* q   = (const float*)d_in[0];
    const float* k   = (const float*)d_in[1];
    const float* v   = (const float*)d_in[2];
    const float* w_q = (const float*)d_in[3];
    const float* w_k = (const float*)d_in[4];
    const float* w_v = (const float*)d_in[5];
    const float* w_o = (const float*)d_in[6];
    float* out = (float*)d_out;

    __half *x16, *w16, *q16, *k16, *v16, *at16;
    cudaGetSymbolAddress((void**)&x16, g_x16);
    cudaGetSymbolAddress((void**)&w16, g_w16);
    cudaGetSymbolAddress((void**)&q16, g_q16);
    cudaGetSymbolAddress((void**)&k16, g_k16);
    cudaGetSymbolAddress((void**)&v16, g_v16);
    cudaGetSymbolAddress((void**)&at16, g_at16);

    cudaFuncSetAttribute(gemm_qkv3, cudaFuncAttributeMaxDynamicSharedMemorySize, SMEM1);
    cudaFuncSetAttribute(gemm_wo, cudaFuncAttributeMaxDynamicSharedMemorySize, SMEM1);
    cudaFuncSetAttribute(fused_attn, cudaFuncAttributeMaxDynamicSharedMemorySize, FA_SMEM);

    const int M_rows = NBATCH * S_LEN;
    const size_t NACT = (size_t)M_rows * DMODEL;
    const size_t NW   = (size_t)DMODEL * DMODEL;
    const int nact4 = (int)(NACT / 4);
    const int nw4   = (int)(NW / 4);
    dim3 blk(256);

    // 1) Round inputs and weights to fp16
    {
        dim3 ga((nact4 + 255) / 256, 3);
        conv_h<<<ga, blk>>>(q, k, v, nullptr,
                            x16, x16 + NACT, x16 + 2 * NACT, nullptr, nact4);
        dim3 gw((nw4 + 255) / 256, 4);
        conv_h<<<gw, blk>>>(w_q, w_k, w_v, w_o,
                            w16, w16 + NW, w16 + 2 * NW, w16 + 3 * NW, nw4);
    }

    // 2) QKV projections (pure fp16 1-pass, one launch)
    {
        dim3 grid(DMODEL / 128, M_rows / 128, 3);
        gemm_qkv3<<<grid, blk, SMEM1>>>(x16, w16, q16, k16, v16);
    }

    // 3) Fused attention: 64 Q-rows per 128-thread CTA, 2 CTAs/SM
    {
        dim3 grid(S_LEN / FA_QROWS, NBATCH * NHEADS);
        fused_attn<<<grid, 128, FA_SMEM>>>(q16, k16, v16, at16);
    }

    // 4) Output projection (pure fp16 1-pass) -> fp32 d_out
    {
        dim3 grid(DMODEL / 128, M_rows / 128);
        gemm_wo<<<grid, blk, SMEM1>>>(at16, w16 + 3 * NW, out);
    }
}